// round 1
// baseline (speedup 1.0000x reference)
#include <cuda_runtime.h>
#include <math.h>
#include <stdint.h>

// Problem constants (fixed-shape problem)
#define Bn 32
#define Tn 2048
#define Dn 1024
#define En 16
#define Ln 8
#define Pmax 720

// ---------------- scratch (static device globals; no allocation) ----------------
__device__ float g_step_base[Pmax * Dn];
__device__ float g_t1[Ln * Dn];
__device__ float g_qeff[Ln * Dn];
__device__ float g_s1[Bn * Ln * Tn];          // scores -> probs (in place)
__device__ float g_upart[4 * Bn * Ln * Dn];   // t-split partials for U
__device__ float g_U[Bn * Ln * Dn];
__device__ float g_tmpA[Bn * Ln * Dn];
__device__ float g_tmpB[Bn * Ln * Dn];
__device__ float g_LC[Bn * Ln * Dn];          // lat_ctx
__device__ float g_k2[Bn * Ln * Dn];
__device__ float g_lvw[Bn * Ln * Dn];         // lat_ctx@lat_v_w@step_out_w@W1b
__device__ float g_qb2[Pmax * Dn];
__device__ float g_baseh[Pmax * Dn];
__device__ float g_A2[Bn * Pmax * Ln];

__device__ __forceinline__ float gelu_f(float x) {
    return 0.5f * x * (1.0f + erff(x * 0.70710678118654752440f));
}

// ---------------- step_base = query_pos[:pl] + pred_len_table[pl] ----------------
__global__ void k_stepbase(const float* __restrict__ qpos,
                           const float* __restrict__ tbl, int pl) {
    int i = blockIdx.x * 256 + threadIdx.x;
    if (i < pl * Dn)
        g_step_base[i] = qpos[i] + tbl[(size_t)pl * Dn + (i & (Dn - 1))];
}

// ---------------- generic fp32 GEMM: C[M,N] = alpha*A@B(^T) (+bias[n]) -----------
// 64x64 tile, BK=16, 256 threads, 4x4 microtile. N multiple of 64, K multiple of 16.
__global__ void k_gemm(const float* __restrict__ A, const float* __restrict__ B,
                       float* __restrict__ C, int M, int N, int K,
                       int transB, const float* __restrict__ bias, float alpha) {
    __shared__ float As[16][68];
    __shared__ float Bs[16][68];
    int tid = threadIdx.x;
    int tx = tid & 15, ty = tid >> 4;
    int m0 = blockIdx.y * 64, n0 = blockIdx.x * 64;
    float acc[4][4];
#pragma unroll
    for (int i = 0; i < 4; i++)
#pragma unroll
        for (int j = 0; j < 4; j++) acc[i][j] = 0.f;

    for (int k0 = 0; k0 < K; k0 += 16) {
#pragma unroll
        for (int r = 0; r < 4; r++) {
            int i = tid + 256 * r;
            int row = i >> 4, col = i & 15;
            int gm = m0 + row;
            As[col][row] = (gm < M) ? A[(size_t)gm * K + k0 + col] : 0.f;
        }
        if (!transB) {
#pragma unroll
            for (int r = 0; r < 4; r++) {
                int i = tid + 256 * r;
                int row = i >> 6, col = i & 63;
                Bs[row][col] = B[(size_t)(k0 + row) * N + n0 + col];
            }
        } else {
#pragma unroll
            for (int r = 0; r < 4; r++) {
                int i = tid + 256 * r;
                int row = i >> 4, col = i & 15;  // row = n (64), col = k (16)
                Bs[col][row] = B[(size_t)(n0 + row) * K + k0 + col];
            }
        }
        __syncthreads();
#pragma unroll
        for (int kk = 0; kk < 16; kk++) {
            float a[4], bb[4];
#pragma unroll
            for (int i = 0; i < 4; i++) a[i] = As[kk][ty * 4 + i];
#pragma unroll
            for (int j = 0; j < 4; j++) bb[j] = Bs[kk][tx * 4 + j];
#pragma unroll
            for (int i = 0; i < 4; i++)
#pragma unroll
                for (int j = 0; j < 4; j++) acc[i][j] += a[i] * bb[j];
        }
        __syncthreads();
    }
#pragma unroll
    for (int i = 0; i < 4; i++) {
        int m = m0 + ty * 4 + i;
        if (m >= M) continue;
#pragma unroll
        for (int j = 0; j < 4; j++) {
            int n = n0 + tx * 4 + j;
            float v = alpha * acc[i][j];
            if (bias) v += bias[n];
            C[(size_t)m * N + n] = v;
        }
    }
}

// ---------------- stage-1 scores: s1[b,l,t] = qeff[l] . ctx[b,t] ------------------
__global__ void k_scores1(const float* __restrict__ ctx) {
    __shared__ float4 q4s[Ln][Dn / 4];  // 32KB
    int tid = threadIdx.x;
    {
        const float4* src = (const float4*)g_qeff;
        float4* dst = (float4*)q4s;
        for (int i = tid; i < Ln * Dn / 4; i += 256) dst[i] = src[i];
    }
    __syncthreads();
    int b = blockIdx.y;
    int w = tid >> 5, lane = tid & 31;
    int t = blockIdx.x * 8 + w;
    const float4* c4 = (const float4*)(ctx + ((size_t)b * Tn + t) * Dn);
    float acc[Ln];
#pragma unroll
    for (int l = 0; l < Ln; l++) acc[l] = 0.f;
#pragma unroll
    for (int i = 0; i < Dn / 4 / 32; i++) {
        float4 c = c4[lane + 32 * i];
#pragma unroll
        for (int l = 0; l < Ln; l++) {
            float4 q = q4s[l][lane + 32 * i];
            acc[l] += c.x * q.x + c.y * q.y + c.z * q.z + c.w * q.w;
        }
    }
#pragma unroll
    for (int l = 0; l < Ln; l++)
        for (int off = 16; off; off >>= 1)
            acc[l] += __shfl_xor_sync(0xffffffffu, acc[l], off);
    if (lane == 0) {
#pragma unroll
        for (int l = 0; l < Ln; l++)
            g_s1[((size_t)b * Ln + l) * Tn + t] = acc[l];
    }
}

// ---------------- softmax over t (rows of 2048), in place -------------------------
__global__ void k_softmax1() {
    __shared__ float red[8];
    size_t base = (size_t)blockIdx.x * Tn;
    int tid = threadIdx.x;
    float4 v0 = ((float4*)(g_s1 + base))[tid * 2];
    float4 v1 = ((float4*)(g_s1 + base))[tid * 2 + 1];
    float m = fmaxf(fmaxf(fmaxf(v0.x, v0.y), fmaxf(v0.z, v0.w)),
                    fmaxf(fmaxf(v1.x, v1.y), fmaxf(v1.z, v1.w)));
    for (int off = 16; off; off >>= 1)
        m = fmaxf(m, __shfl_xor_sync(0xffffffffu, m, off));
    if ((tid & 31) == 0) red[tid >> 5] = m;
    __syncthreads();
    m = red[0];
#pragma unroll
    for (int w = 1; w < 8; w++) m = fmaxf(m, red[w]);
    __syncthreads();
    v0.x = expf(v0.x - m); v0.y = expf(v0.y - m);
    v0.z = expf(v0.z - m); v0.w = expf(v0.w - m);
    v1.x = expf(v1.x - m); v1.y = expf(v1.y - m);
    v1.z = expf(v1.z - m); v1.w = expf(v1.w - m);
    float s = v0.x + v0.y + v0.z + v0.w + v1.x + v1.y + v1.z + v1.w;
    for (int off = 16; off; off >>= 1)
        s += __shfl_xor_sync(0xffffffffu, s, off);
    if ((tid & 31) == 0) red[tid >> 5] = s;
    __syncthreads();
    float tot = red[0];
#pragma unroll
    for (int w = 1; w < 8; w++) tot += red[w];
    v0.x /= tot; v0.y /= tot; v0.z /= tot; v0.w /= tot;
    v1.x /= tot; v1.y /= tot; v1.z /= tot; v1.w /= tot;
    ((float4*)(g_s1 + base))[tid * 2] = v0;
    ((float4*)(g_s1 + base))[tid * 2 + 1] = v1;
}

// ---------------- U = probs @ ctx (t-split partials, deterministic) ---------------
// grid (8 dchunk, 4 tseg, 32 b), 128 threads
__global__ void k_upart(const float* __restrict__ ctx) {
    __shared__ float ps[Ln][256];
    int d = blockIdx.x * 128 + threadIdx.x;
    int b = blockIdx.z, tseg = blockIdx.y;
    float acc[Ln];
#pragma unroll
    for (int l = 0; l < Ln; l++) acc[l] = 0.f;
    for (int t0 = tseg * 512; t0 < tseg * 512 + 512; t0 += 256) {
        __syncthreads();
        for (int i = threadIdx.x; i < Ln * 256; i += 128) {
            int l = i >> 8, tt = i & 255;
            ps[l][tt] = g_s1[((size_t)b * Ln + l) * Tn + t0 + tt];
        }
        __syncthreads();
#pragma unroll 4
        for (int tt = 0; tt < 256; tt++) {
            float c = ctx[((size_t)b * Tn + t0 + tt) * Dn + d];
#pragma unroll
            for (int l = 0; l < Ln; l++) acc[l] += ps[l][tt] * c;
        }
    }
#pragma unroll
    for (int l = 0; l < Ln; l++)
        g_upart[(((size_t)tseg * Bn + b) * Ln + l) * Dn + d] = acc[l];
}

__global__ void k_ureduce() {
    int i = blockIdx.x * 256 + threadIdx.x;
    const int S = Bn * Ln * Dn;
    g_U[i] = g_upart[i] + g_upart[i + S] + g_upart[i + 2 * S] + g_upart[i + 3 * S];
}

// ---------------- stage-2 scores + softmax over L=8 -------------------------------
// grid ((pl+7)/8, B), 256 threads; warp w handles row p
__global__ void k_s2(int pl) {
    __shared__ float4 k2s[Ln][Dn / 4];  // 32KB
    int tid = threadIdx.x;
    int b = blockIdx.y;
    {
        const float4* src = (const float4*)(g_k2 + (size_t)b * Ln * Dn);
        float4* dst = (float4*)k2s;
        for (int i = tid; i < Ln * Dn / 4; i += 256) dst[i] = src[i];
    }
    __syncthreads();
    int w = tid >> 5, lane = tid & 31;
    int p = blockIdx.x * 8 + w;
    if (p >= pl) return;
    const float4* q4 = (const float4*)(g_qb2 + (size_t)p * Dn);
    float acc[Ln];
#pragma unroll
    for (int l = 0; l < Ln; l++) acc[l] = 0.f;
#pragma unroll
    for (int i = 0; i < Dn / 4 / 32; i++) {
        float4 q = q4[lane + 32 * i];
#pragma unroll
        for (int l = 0; l < Ln; l++) {
            float4 k = k2s[l][lane + 32 * i];
            acc[l] += q.x * k.x + q.y * k.y + q.z * k.z + q.w * k.w;
        }
    }
#pragma unroll
    for (int l = 0; l < Ln; l++)
        for (int off = 16; off; off >>= 1)
            acc[l] += __shfl_xor_sync(0xffffffffu, acc[l], off);
    if (lane == 0) {
        float m = acc[0];
#pragma unroll
        for (int l = 1; l < Ln; l++) m = fmaxf(m, acc[l]);
        float e[Ln], s = 0.f;
#pragma unroll
        for (int l = 0; l < Ln; l++) { e[l] = expf(acc[l] - m); s += e[l]; }
#pragma unroll
        for (int l = 0; l < Ln; l++)
            g_A2[((size_t)b * pl + p) * Ln + l] = e[l] / s;
    }
}

// ---------------- fused gate: h=gelu(base_h + A2@lvw), logits, top2, combine -----
// grid ((pl+7)/8, B), 256 threads, dynamic shared ~104KB
__global__ void k_final(const float* __restrict__ w2, const float* __restrict__ b2,
                        const float* __restrict__ qexp, float* __restrict__ out,
                        int pl, int Pfull) {
    extern __shared__ float sm[];
    float* lvws = sm;                    // 8192
    float* w2s  = lvws + Ln * Dn;        // 16384
    float* hs   = w2s + Dn * En;         // 1024
    float* a2s  = hs + Dn;               // 64
    float* part = a2s + 64;              // 16*17 = 272
    float* lg   = part + 272;            // 16
    float* wsel = lg + 16;               // 4
    int tid = threadIdx.x;
    int b = blockIdx.y;
    int p0 = blockIdx.x * 8;
    {
        const float4* src = (const float4*)(g_lvw + (size_t)b * Ln * Dn);
        float4* dst = (float4*)lvws;
        for (int i = tid; i < Ln * Dn / 4; i += 256) dst[i] = src[i];
        const float4* wg = (const float4*)w2;
        float4* wd = (float4*)w2s;
        for (int i = tid; i < Dn * En / 4; i += 256) wd[i] = wg[i];
        if (tid < 64) {
            int pi = tid >> 3, l = tid & 7;
            int p = p0 + pi;
            a2s[tid] = (p < pl) ? g_A2[((size_t)b * pl + p) * Ln + l] : 0.f;
        }
    }
    __syncthreads();
    int e_id = tid & 15, dseg = tid >> 4;
    for (int pi = 0; pi < 8; pi++) {
        int p = p0 + pi;
        if (p >= pl) break;  // block-uniform
        float4 s4 = ((const float4*)(g_baseh + (size_t)p * Dn))[tid];
#pragma unroll
        for (int l = 0; l < Ln; l++) {
            float a = a2s[pi * 8 + l];
            float4 v = ((const float4*)lvws)[l * (Dn / 4) + tid];
            s4.x += a * v.x; s4.y += a * v.y; s4.z += a * v.z; s4.w += a * v.w;
        }
        float4 h4;
        h4.x = gelu_f(s4.x); h4.y = gelu_f(s4.y);
        h4.z = gelu_f(s4.z); h4.w = gelu_f(s4.w);
        ((float4*)hs)[tid] = h4;
        __syncthreads();
        // logits partial: this thread handles expert e_id over d in [dseg*64, dseg*64+64)
        float lacc = 0.f;
        int dbase = dseg * 64;
#pragma unroll 4
        for (int d = 0; d < 64; d++)
            lacc += hs[dbase + d] * w2s[(dbase + d) * En + e_id];
        part[dseg * 17 + e_id] = lacc;
        __syncthreads();
        if (tid < En) {
            float L = b2[tid];
#pragma unroll
            for (int g = 0; g < 16; g++) L += part[g * 17 + tid];
            lg[tid] = L;
        }
        __syncthreads();
        if (tid == 0) {
            float b1v = lg[0]; int e1 = 0;
#pragma unroll
            for (int e = 1; e < En; e++) if (lg[e] > b1v) { b1v = lg[e]; e1 = e; }
            float b2v = -3.4e38f; int e2 = 0;
#pragma unroll
            for (int e = 0; e < En; e++)
                if (e != e1 && lg[e] > b2v) { b2v = lg[e]; e2 = e; }
            float x2 = expf(b2v - b1v);
            float s = 1.f + x2;
            wsel[0] = 1.f / s; wsel[1] = x2 / s;
            ((int*)wsel)[2] = e1; ((int*)wsel)[3] = e2;
        }
        __syncthreads();
        float wA = wsel[0], wB = wsel[1];
        int eA = ((int*)wsel)[2], eB = ((int*)wsel)[3];
        const float4* qa = (const float4*)(qexp + ((size_t)eA * Pfull + p) * Dn);
        const float4* qb = (const float4*)(qexp + ((size_t)eB * Pfull + p) * Dn);
        float4 va = qa[tid], vb = qb[tid];
        float4 o;
        o.x = wA * va.x + wB * vb.x;
        o.y = wA * va.y + wB * vb.y;
        o.z = wA * va.z + wB * vb.z;
        o.w = wA * va.w + wB * vb.w;
        ((float4*)(out + ((size_t)b * pl + p) * Dn))[tid] = o;
        __syncthreads();
    }
}

// ---------------- launch -----------------------------------------------------------
extern "C" void kernel_launch(void* const* d_in, const int* in_sizes, int n_in,
                              void* d_out, int out_size) {
    const float* ctx        = (const float*)d_in[0];
    const float* qexp       = (const float*)d_in[1];
    const float* qpos       = (const float*)d_in[2];
    const float* ptbl       = (const float*)d_in[3];
    const float* lats       = (const float*)d_in[4];
    const float* lat_q_w    = (const float*)d_in[5];
    const float* ctx_k_w    = (const float*)d_in[6];
    const float* ctx_v_w    = (const float*)d_in[7];
    const float* lat_out_w  = (const float*)d_in[8];
    const float* step_q_w   = (const float*)d_in[9];
    const float* lat_k_w    = (const float*)d_in[10];
    const float* lat_v_w    = (const float*)d_in[11];
    const float* step_out_w = (const float*)d_in[12];
    const float* gate_w1    = (const float*)d_in[13];
    const float* gate_b1    = (const float*)d_in[14];
    const float* gate_w2    = (const float*)d_in[15];
    const float* gate_b2    = (const float*)d_in[16];
    float* out = (float*)d_out;

    int pl = out_size / (Bn * Dn);       // pred_len (720 for this problem)
    int Pfull = in_sizes[2] / Dn;        // rows of query_pos / query_experts

    float *p_t1, *p_qeff, *p_U, *p_tmpA, *p_tmpB, *p_LC, *p_k2, *p_lvw;
    float *p_sb, *p_qb2, *p_bh;
    cudaGetSymbolAddress((void**)&p_t1, g_t1);
    cudaGetSymbolAddress((void**)&p_qeff, g_qeff);
    cudaGetSymbolAddress((void**)&p_U, g_U);
    cudaGetSymbolAddress((void**)&p_tmpA, g_tmpA);
    cudaGetSymbolAddress((void**)&p_tmpB, g_tmpB);
    cudaGetSymbolAddress((void**)&p_LC, g_LC);
    cudaGetSymbolAddress((void**)&p_k2, g_k2);
    cudaGetSymbolAddress((void**)&p_lvw, g_lvw);
    cudaGetSymbolAddress((void**)&p_sb, g_step_base);
    cudaGetSymbolAddress((void**)&p_qb2, g_qb2);
    cudaGetSymbolAddress((void**)&p_bh, g_baseh);

    const float inv_sqrt_d = 0.03125f;  // 1/sqrt(1024)

    // step_base (batch-independent)
    k_stepbase<<<(pl * Dn + 255) / 256, 256>>>(qpos, ptbl, pl);

    // qeff = (latents @ lat_q_w) @ ctx_k_w^T * (1/sqrt(D))
    k_gemm<<<dim3(Dn / 64, 1), 256>>>(lats, lat_q_w, p_t1, Ln, Dn, Dn, 0, nullptr, 1.f);
    k_gemm<<<dim3(Dn / 64, 1), 256>>>(p_t1, ctx_k_w, p_qeff, Ln, Dn, Dn, 1, nullptr, inv_sqrt_d);

    // stage-1 attention over ctx (two memory passes)
    k_scores1<<<dim3(Tn / 8, Bn), 256>>>(ctx);
    k_softmax1<<<Bn * Ln, 256>>>();
    k_upart<<<dim3(8, 4, Bn), 128>>>(ctx);
    k_ureduce<<<Bn * Ln * Dn / 256, 256>>>();

    // lat_ctx = (U @ ctx_v_w) @ lat_out_w ; stacked [B*L, D]
    k_gemm<<<dim3(16, 4), 256>>>(p_U, ctx_v_w, p_tmpA, Bn * Ln, Dn, Dn, 0, nullptr, 1.f);
    k_gemm<<<dim3(16, 4), 256>>>(p_tmpA, lat_out_w, p_LC, Bn * Ln, Dn, Dn, 0, nullptr, 1.f);
    // k2 = lat_ctx @ lat_k_w
    k_gemm<<<dim3(16, 4), 256>>>(p_LC, lat_k_w, p_k2, Bn * Ln, Dn, Dn, 0, nullptr, 1.f);
    // lvw = ((lat_ctx @ lat_v_w) @ step_out_w) @ W1b
    k_gemm<<<dim3(16, 4), 256>>>(p_LC, lat_v_w, p_tmpA, Bn * Ln, Dn, Dn, 0, nullptr, 1.f);
    k_gemm<<<dim3(16, 4), 256>>>(p_tmpA, step_out_w, p_tmpB, Bn * Ln, Dn, Dn, 0, nullptr, 1.f);
    k_gemm<<<dim3(16, 4), 256>>>(p_tmpB, gate_w1 + (size_t)Dn * Dn, p_lvw, Bn * Ln, Dn, Dn, 0, nullptr, 1.f);

    // batch-independent [P,D] GEMMs
    int gy = (pl + 63) / 64;
    k_gemm<<<dim3(16, gy), 256>>>(p_sb, step_q_w, p_qb2, pl, Dn, Dn, 0, nullptr, inv_sqrt_d);
    k_gemm<<<dim3(16, gy), 256>>>(p_sb, gate_w1, p_bh, pl, Dn, Dn, 0, gate_b1, 1.f);

    // stage-2 attention weights
    k_s2<<<dim3((pl + 7) / 8, Bn), 256>>>(pl);

    // fused gate + top2 + expert combine
    const int smem_final = (Ln * Dn + Dn * En + Dn + 64 + 272 + 16 + 4) * 4;
    cudaFuncSetAttribute(k_final, cudaFuncAttributeMaxDynamicSharedMemorySize, smem_final);
    k_final<<<dim3((pl + 7) / 8, Bn), 256, smem_final>>>(gate_w2, gate_b2, qexp, out, pl, Pfull);
}

// round 2
// speedup vs baseline: 1.4336x; 1.4336x over previous
#include <cuda_runtime.h>
#include <math.h>
#include <stdint.h>

#define Bn 32
#define Tn 2048
#define Dn 1024
#define En 16
#define Ln 8
#define Pmax 720

typedef unsigned long long ull;

__device__ __forceinline__ void fma2(ull& d, ull a, ull b) {
    asm("fma.rn.f32x2 %0, %1, %2, %0;" : "+l"(d) : "l"(a), "l"(b));
}
__device__ __forceinline__ float2 u2f(ull v) {
    float2 f; asm("mov.b64 {%0,%1}, %2;" : "=f"(f.x), "=f"(f.y) : "l"(v)); return f;
}
__device__ __forceinline__ float gelu_f(float x) {
    return 0.5f * x * (1.0f + erff(x * 0.70710678118654752440f));
}

// ---------------- scratch ----------------
__device__ float g_step_base[Pmax * Dn];
__device__ float g_t1p[8 * Ln * Dn];
__device__ float g_qeffp[8 * Ln * Dn];
__device__ float g_qeff[Ln * Dn];
__device__ float g_s1[Bn * Ln * Tn];
__device__ float g_upart[8 * Bn * Ln * Dn];
__device__ float g_pA[4 * Bn * Ln * Dn];
__device__ float g_pLC[4 * Bn * Ln * Dn];
__device__ float g_pk2[4 * Bn * Ln * Dn];
__device__ float g_pB[4 * Bn * Ln * Dn];
__device__ float g_pC[4 * Bn * Ln * Dn];
__device__ float g_plvw[4 * Bn * Ln * Dn];
__device__ float g_k2[Bn * Ln * Dn];
__device__ float g_lvw[Bn * Ln * Dn];
__device__ float g_qb2p[2 * Pmax * Dn];
__device__ float g_bhp[2 * Pmax * Dn];
__device__ float g_qb2[Pmax * Dn];
__device__ float g_bh[Pmax * Dn];
__device__ float g_A2[Bn * Pmax * Ln];

// ---------------- step_base ----------------
__global__ void k_stepbase(const float* __restrict__ qpos,
                           const float* __restrict__ tbl, int pl) {
    int i = blockIdx.x * 256 + threadIdx.x;
    if (i < pl * Dn)
        g_step_base[i] = qpos[i] + tbl[(size_t)pl * Dn + (i & (Dn - 1))];
}

// ---------------- split-K fp32x2 GEMM ----------------
// C_part[z][M,N] = alpha * A@B(^T) over k-range z. 64x64 tile, BK=16,
// 256 threads, 4x4 micro via fma.f32x2 (A duplicated in smem), double-buffered.
// nsumA: A is the sum of nsumA partials spaced strideA elements apart.
#define GEMM_PREFETCH(k0)                                                        \
    {                                                                            \
        for (int r = 0; r < 4; r++) {                                            \
            int i = tid + 256 * r;                                               \
            int row = i >> 4, col = i & 15;                                      \
            int gm = m0 + row;                                                   \
            float v = 0.f;                                                       \
            if (gm < M) {                                                        \
                size_t off = (size_t)gm * K + (k0) + col;                        \
                v = A[off];                                                      \
                for (int s = 1; s < nsumA; s++) v += A[off + (size_t)s * strideA]; \
            }                                                                    \
            ra[r] = v;                                                           \
        }                                                                        \
        if (!transB) {                                                           \
            for (int r = 0; r < 4; r++) {                                        \
                int i = tid + 256 * r;                                           \
                rb[r] = B[(size_t)((k0) + (i >> 6)) * N + n0 + (i & 63)];        \
            }                                                                    \
        } else {                                                                 \
            for (int r = 0; r < 4; r++) {                                        \
                int i = tid + 256 * r;                                           \
                rb[r] = B[(size_t)(n0 + (i >> 4)) * K + (k0) + (i & 15)];        \
            }                                                                    \
        }                                                                        \
    }

#define GEMM_STORE(bf)                                                           \
    {                                                                            \
        for (int r = 0; r < 4; r++) {                                            \
            int i = tid + 256 * r;                                               \
            *(float2*)&As2[bf][i & 15][2 * (i >> 4)] = make_float2(ra[r], ra[r]); \
        }                                                                        \
        if (!transB) {                                                           \
            for (int r = 0; r < 4; r++) {                                        \
                int i = tid + 256 * r;                                           \
                Bs[bf][i >> 6][i & 63] = rb[r];                                  \
            }                                                                    \
        } else {                                                                 \
            for (int r = 0; r < 4; r++) {                                        \
                int i = tid + 256 * r;                                           \
                Bs[bf][i & 15][i >> 4] = rb[r];                                  \
            }                                                                    \
        }                                                                        \
    }

#define GEMM_COMPUTE(bf)                                                         \
    {                                                                            \
        _Pragma("unroll")                                                        \
        for (int kk = 0; kk < 16; kk++) {                                        \
            ulonglong2 a01 = *(const ulonglong2*)&As2[bf][kk][ty * 8];           \
            ulonglong2 a23 = *(const ulonglong2*)&As2[bf][kk][ty * 8 + 4];       \
            ulonglong2 bb  = *(const ulonglong2*)&Bs[bf][kk][tx * 4];            \
            fma2(acc[0][0], a01.x, bb.x); fma2(acc[0][1], a01.x, bb.y);          \
            fma2(acc[1][0], a01.y, bb.x); fma2(acc[1][1], a01.y, bb.y);          \
            fma2(acc[2][0], a23.x, bb.x); fma2(acc[2][1], a23.x, bb.y);          \
            fma2(acc[3][0], a23.y, bb.x); fma2(acc[3][1], a23.y, bb.y);          \
        }                                                                        \
    }

__global__ void k_gemm(const float* __restrict__ A, const float* __restrict__ B,
                       float* __restrict__ C, int M, int N, int K,
                       int transB, const float* __restrict__ bias, float alpha,
                       int nsumA, int strideA) {
    __shared__ float As2[2][16][136];
    __shared__ float Bs[2][16][68];
    int tid = threadIdx.x;
    int tx = tid & 15, ty = tid >> 4;
    int m0 = blockIdx.y * 64, n0 = blockIdx.x * 64;
    int kper = K / gridDim.z;
    int kbeg = blockIdx.z * kper;
    C += (size_t)blockIdx.z * M * N;
    int nk = kper / 16;

    ull acc[4][2];
#pragma unroll
    for (int i = 0; i < 4; i++) { acc[i][0] = 0ULL; acc[i][1] = 0ULL; }

    float ra[4], rb[4];
    int buf = 0;
    GEMM_PREFETCH(kbeg);
    GEMM_STORE(0);
    __syncthreads();
    for (int kt = 0; kt < nk; kt++) {
        if (kt + 1 < nk) GEMM_PREFETCH(kbeg + (kt + 1) * 16);
        GEMM_COMPUTE(buf);
        if (kt + 1 < nk) {
            GEMM_STORE(buf ^ 1);
            __syncthreads();
            buf ^= 1;
        }
    }
#pragma unroll
    for (int i = 0; i < 4; i++) {
        int m = m0 + ty * 4 + i;
        if (m >= M) continue;
        float2 p0 = u2f(acc[i][0]), p1 = u2f(acc[i][1]);
        float4 o;
        o.x = alpha * p0.x; o.y = alpha * p0.y;
        o.z = alpha * p1.x; o.w = alpha * p1.y;
        if (bias) {
            o.x += bias[n0 + tx * 4];     o.y += bias[n0 + tx * 4 + 1];
            o.z += bias[n0 + tx * 4 + 2]; o.w += bias[n0 + tx * 4 + 3];
        }
        *(float4*)&C[(size_t)m * N + n0 + tx * 4] = o;
    }
}

// ---------------- generic partial reduction ----------------
__global__ void k_redN(float4* __restrict__ dst, const float4* __restrict__ src,
                       int n4, int nparts, int stride4) {
    int i = blockIdx.x * 256 + threadIdx.x;
    if (i >= n4) return;
    float4 s = src[i];
    for (int p = 1; p < nparts; p++) {
        float4 t = src[i + (size_t)p * stride4];
        s.x += t.x; s.y += t.y; s.z += t.z; s.w += t.w;
    }
    dst[i] = s;
}

// ---------------- stage-1 scores: 4 t per warp, f32x2 ----------------
__global__ void k_scores1(const float* __restrict__ ctx) {
    __shared__ float qs[Ln][Dn];  // 32KB
    int tid = threadIdx.x;
    for (int i = tid; i < Ln * Dn / 4; i += 256)
        ((float4*)qs)[i] = ((const float4*)g_qeff)[i];
    __syncthreads();
    int b = blockIdx.y, w = tid >> 5, lane = tid & 31;
    int t0 = (blockIdx.x * 8 + w) * 4;
    const float* base = ctx + ((size_t)b * Tn + t0) * Dn;
    ull acc[4][Ln];
#pragma unroll
    for (int tt = 0; tt < 4; tt++)
#pragma unroll
        for (int l = 0; l < Ln; l++) acc[tt][l] = 0ULL;
#pragma unroll
    for (int i = 0; i < 8; i++) {
        int d = (lane + 32 * i) * 4;
        ulonglong2 c0 = *(const ulonglong2*)(base + d);
        ulonglong2 c1 = *(const ulonglong2*)(base + Dn + d);
        ulonglong2 c2 = *(const ulonglong2*)(base + 2 * Dn + d);
        ulonglong2 c3 = *(const ulonglong2*)(base + 3 * Dn + d);
#pragma unroll
        for (int l = 0; l < Ln; l++) {
            ulonglong2 q = *(const ulonglong2*)&qs[l][d];
            fma2(acc[0][l], c0.x, q.x); fma2(acc[0][l], c0.y, q.y);
            fma2(acc[1][l], c1.x, q.x); fma2(acc[1][l], c1.y, q.y);
            fma2(acc[2][l], c2.x, q.x); fma2(acc[2][l], c2.y, q.y);
            fma2(acc[3][l], c3.x, q.x); fma2(acc[3][l], c3.y, q.y);
        }
    }
#pragma unroll
    for (int tt = 0; tt < 4; tt++)
#pragma unroll
        for (int l = 0; l < Ln; l++) {
            float2 f = u2f(acc[tt][l]);
            float v = f.x + f.y;
            for (int off = 16; off; off >>= 1)
                v += __shfl_xor_sync(0xffffffffu, v, off);
            if (lane == 0)
                g_s1[((size_t)b * Ln + l) * Tn + t0 + tt] = v;
        }
}

// ---------------- softmax over t ----------------
__global__ void k_softmax1() {
    __shared__ float red[8];
    size_t base = (size_t)blockIdx.x * Tn;
    int tid = threadIdx.x;
    float4 v0 = ((float4*)(g_s1 + base))[tid * 2];
    float4 v1 = ((float4*)(g_s1 + base))[tid * 2 + 1];
    float m = fmaxf(fmaxf(fmaxf(v0.x, v0.y), fmaxf(v0.z, v0.w)),
                    fmaxf(fmaxf(v1.x, v1.y), fmaxf(v1.z, v1.w)));
    for (int off = 16; off; off >>= 1)
        m = fmaxf(m, __shfl_xor_sync(0xffffffffu, m, off));
    if ((tid & 31) == 0) red[tid >> 5] = m;
    __syncthreads();
    m = red[0];
#pragma unroll
    for (int w = 1; w < 8; w++) m = fmaxf(m, red[w]);
    __syncthreads();
    v0.x = expf(v0.x - m); v0.y = expf(v0.y - m);
    v0.z = expf(v0.z - m); v0.w = expf(v0.w - m);
    v1.x = expf(v1.x - m); v1.y = expf(v1.y - m);
    v1.z = expf(v1.z - m); v1.w = expf(v1.w - m);
    float s = v0.x + v0.y + v0.z + v0.w + v1.x + v1.y + v1.z + v1.w;
    for (int off = 16; off; off >>= 1)
        s += __shfl_xor_sync(0xffffffffu, s, off);
    if ((tid & 31) == 0) red[tid >> 5] = s;
    __syncthreads();
    float tot = red[0];
#pragma unroll
    for (int w = 1; w < 8; w++) tot += red[w];
    float inv = 1.0f / tot;
    v0.x *= inv; v0.y *= inv; v0.z *= inv; v0.w *= inv;
    v1.x *= inv; v1.y *= inv; v1.z *= inv; v1.w *= inv;
    ((float4*)(g_s1 + base))[tid * 2] = v0;
    ((float4*)(g_s1 + base))[tid * 2 + 1] = v1;
}

// ---------------- U partials = probs @ ctx (8 t-segments) ----------------
// grid (2, 8, 32), 128 threads; thread owns 4 d via float4
__global__ void k_upart(const float* __restrict__ ctx) {
    __shared__ float ps2[Ln][512];  // duplicated probs
    int tid = threadIdx.x;
    int b = blockIdx.z, tseg = blockIdx.y;
    int d = (blockIdx.x * 128 + tid) * 4;
    int t0 = tseg * 256;
    for (int i = tid; i < Ln * 256; i += 128) {
        int l = i >> 8, tt = i & 255;
        float p = g_s1[((size_t)b * Ln + l) * Tn + t0 + tt];
        *(float2*)&ps2[l][2 * tt] = make_float2(p, p);
    }
    __syncthreads();
    ull acc[Ln][2];
#pragma unroll
    for (int l = 0; l < Ln; l++) { acc[l][0] = 0ULL; acc[l][1] = 0ULL; }
    const float* cb = ctx + ((size_t)b * Tn + t0) * Dn + d;
    for (int tt = 0; tt < 256; tt++) {
        ulonglong2 c = *(const ulonglong2*)(cb + (size_t)tt * Dn);
#pragma unroll
        for (int l = 0; l < Ln; l++) {
            ull p = *(const ull*)&ps2[l][2 * tt];
            fma2(acc[l][0], p, c.x);
            fma2(acc[l][1], p, c.y);
        }
    }
#pragma unroll
    for (int l = 0; l < Ln; l++) {
        float2 f0 = u2f(acc[l][0]), f1 = u2f(acc[l][1]);
        *(float4*)&g_upart[(((size_t)tseg * Bn + b) * Ln + l) * Dn + d] =
            make_float4(f0.x, f0.y, f1.x, f1.y);
    }
}

// ---------------- stage-2 scores + softmax over L=8 ----------------
// grid ((pl+15)/16, B), 256 threads, each warp 2 p
__global__ void k_s2(int pl) {
    __shared__ float ks[Ln][Dn];  // 32KB
    int tid = threadIdx.x, b = blockIdx.y;
    for (int i = tid; i < Ln * Dn / 4; i += 256)
        ((float4*)ks)[i] = ((const float4*)(g_k2 + (size_t)b * Ln * Dn))[i];
    __syncthreads();
    int w = tid >> 5, lane = tid & 31;
    int p0 = blockIdx.x * 16 + w * 2;
    if (p0 > Pmax - 2) p0 = Pmax - 2;
    ull acc[2][Ln];
#pragma unroll
    for (int pp = 0; pp < 2; pp++)
#pragma unroll
        for (int l = 0; l < Ln; l++) acc[pp][l] = 0ULL;
#pragma unroll
    for (int i = 0; i < 8; i++) {
        int d = (lane + 32 * i) * 4;
        ulonglong2 q0 = *(const ulonglong2*)(g_qb2 + (size_t)p0 * Dn + d);
        ulonglong2 q1 = *(const ulonglong2*)(g_qb2 + (size_t)(p0 + 1) * Dn + d);
#pragma unroll
        for (int l = 0; l < Ln; l++) {
            ulonglong2 k = *(const ulonglong2*)&ks[l][d];
            fma2(acc[0][l], q0.x, k.x); fma2(acc[0][l], q0.y, k.y);
            fma2(acc[1][l], q1.x, k.x); fma2(acc[1][l], q1.y, k.y);
        }
    }
#pragma unroll
    for (int pp = 0; pp < 2; pp++) {
        float v[Ln];
#pragma unroll
        for (int l = 0; l < Ln; l++) {
            float2 f = u2f(acc[pp][l]);
            float s = f.x + f.y;
            for (int off = 16; off; off >>= 1)
                s += __shfl_xor_sync(0xffffffffu, s, off);
            v[l] = s;
        }
        if (lane == 0) {
            int p = p0 + pp;
            if (p < pl) {
                float m = v[0];
#pragma unroll
                for (int l = 1; l < Ln; l++) m = fmaxf(m, v[l]);
                float e[Ln], s = 0.f;
#pragma unroll
                for (int l = 0; l < Ln; l++) { e[l] = expf(v[l] - m); s += e[l]; }
                float inv = 1.0f / s;
#pragma unroll
                for (int l = 0; l < Ln; l++)
                    g_A2[((size_t)b * pl + p) * Ln + l] = e[l] * inv;
            }
        }
    }
}

// ---------------- fused gate + top2 + expert combine ----------------
__global__ void k_final(const float* __restrict__ w2, const float* __restrict__ b2,
                        const float* __restrict__ b1, const float* __restrict__ qexp,
                        float* __restrict__ out, int pl, int Pfull) {
    extern __shared__ float sm[];
    float* lvws = sm;                    // 8192
    float* w2T  = lvws + Ln * Dn;        // 16*1026 = 16416
    float* hs   = w2T + 16 * 1026;       // 1024
    float* a2s  = hs + Dn;               // 64
    float* part = a2s + 64;              // 272
    float* lg   = part + 272;            // 16
    float* wsel = lg + 16;               // 4
    int tid = threadIdx.x, b = blockIdx.y, p0 = blockIdx.x * 8;
    for (int i = tid; i < Ln * Dn / 4; i += 256)
        ((float4*)lvws)[i] = ((const float4*)(g_lvw + (size_t)b * Ln * Dn))[i];
    for (int i = tid; i < Dn * En; i += 256) {
        int d = i >> 4, e = i & 15;
        w2T[e * 1026 + d] = w2[i];
    }
    if (tid < 64) {
        int pi = tid >> 3, l = tid & 7;
        int p = p0 + pi;
        a2s[tid] = (p < pl) ? g_A2[((size_t)b * pl + p) * Ln + l] : 0.f;
    }
    __syncthreads();
    float4 b1v = *(const float4*)(b1 + tid * 4);
    int e_id = tid & 15, dseg = tid >> 4;
    for (int pi = 0; pi < 8; pi++) {
        int p = p0 + pi;
        if (p >= pl) break;  // block-uniform
        float4 s4 = *(const float4*)(g_bh + (size_t)p * Dn + tid * 4);
        s4.x += b1v.x; s4.y += b1v.y; s4.z += b1v.z; s4.w += b1v.w;
#pragma unroll
        for (int l = 0; l < Ln; l++) {
            float a = a2s[pi * 8 + l];
            float4 v = ((const float4*)lvws)[l * (Dn / 4) + tid];
            s4.x += a * v.x; s4.y += a * v.y; s4.z += a * v.z; s4.w += a * v.w;
        }
        float4 h4;
        h4.x = gelu_f(s4.x); h4.y = gelu_f(s4.y);
        h4.z = gelu_f(s4.z); h4.w = gelu_f(s4.w);
        ((float4*)hs)[tid] = h4;
        __syncthreads();
        ull lacc = 0ULL;
        int dbase = dseg * 64;
#pragma unroll
        for (int j = 0; j < 32; j++) {
            ull h2 = *(const ull*)&hs[dbase + 2 * j];
            ull wv = *(const ull*)&w2T[e_id * 1026 + dbase + 2 * j];
            fma2(lacc, h2, wv);
        }
        float2 lf = u2f(lacc);
        part[dseg * 17 + e_id] = lf.x + lf.y;
        __syncthreads();
        if (tid < En) {
            float L = b2[tid];
#pragma unroll
            for (int g = 0; g < 16; g++) L += part[g * 17 + tid];
            lg[tid] = L;
        }
        __syncthreads();
        if (tid == 0) {
            float b1s = lg[0]; int e1 = 0;
#pragma unroll
            for (int e = 1; e < En; e++) if (lg[e] > b1s) { b1s = lg[e]; e1 = e; }
            float b2s = -3.4e38f; int e2 = 0;
#pragma unroll
            for (int e = 0; e < En; e++)
                if (e != e1 && lg[e] > b2s) { b2s = lg[e]; e2 = e; }
            float x2 = expf(b2s - b1s);
            float s = 1.f + x2;
            wsel[0] = 1.f / s; wsel[1] = x2 / s;
            ((int*)wsel)[2] = e1; ((int*)wsel)[3] = e2;
        }
        __syncthreads();
        float wA = wsel[0], wB = wsel[1];
        int eA = ((int*)wsel)[2], eB = ((int*)wsel)[3];
        const float4* qa = (const float4*)(qexp + ((size_t)eA * Pfull + p) * Dn);
        const float4* qb = (const float4*)(qexp + ((size_t)eB * Pfull + p) * Dn);
        float4 va = qa[tid], vb = qb[tid];
        float4 o;
        o.x = wA * va.x + wB * vb.x;
        o.y = wA * va.y + wB * vb.y;
        o.z = wA * va.z + wB * vb.z;
        o.w = wA * va.w + wB * vb.w;
        *(float4*)(out + ((size_t)b * pl + p) * Dn + tid * 4) = o;
        __syncthreads();
    }
}

// ---------------- launch ----------------
extern "C" void kernel_launch(void* const* d_in, const int* in_sizes, int n_in,
                              void* d_out, int out_size) {
    const float* ctx        = (const float*)d_in[0];
    const float* qexp       = (const float*)d_in[1];
    const float* qpos       = (const float*)d_in[2];
    const float* ptbl       = (const float*)d_in[3];
    const float* lats       = (const float*)d_in[4];
    const float* lat_q_w    = (const float*)d_in[5];
    const float* ctx_k_w    = (const float*)d_in[6];
    const float* ctx_v_w    = (const float*)d_in[7];
    const float* lat_out_w  = (const float*)d_in[8];
    const float* step_q_w   = (const float*)d_in[9];
    const float* lat_k_w    = (const float*)d_in[10];
    const float* lat_v_w    = (const float*)d_in[11];
    const float* step_out_w = (const float*)d_in[12];
    const float* gate_w1    = (const float*)d_in[13];
    const float* gate_b1    = (const float*)d_in[14];
    const float* gate_w2    = (const float*)d_in[15];
    const float* gate_b2    = (const float*)d_in[16];
    float* out = (float*)d_out;

    int pl = out_size / (Bn * Dn);
    int Pfull = in_sizes[2] / Dn;

    float *p_t1p, *p_qeffp, *p_qeff, *p_up;
    float *p_pA, *p_pLC, *p_pk2, *p_pB, *p_pC, *p_plvw;
    float *p_k2, *p_lvw, *p_sb, *p_qb2p, *p_bhp, *p_qb2, *p_bh;
    cudaGetSymbolAddress((void**)&p_t1p, g_t1p);
    cudaGetSymbolAddress((void**)&p_qeffp, g_qeffp);
    cudaGetSymbolAddress((void**)&p_qeff, g_qeff);
    cudaGetSymbolAddress((void**)&p_up, g_upart);
    cudaGetSymbolAddress((void**)&p_pA, g_pA);
    cudaGetSymbolAddress((void**)&p_pLC, g_pLC);
    cudaGetSymbolAddress((void**)&p_pk2, g_pk2);
    cudaGetSymbolAddress((void**)&p_pB, g_pB);
    cudaGetSymbolAddress((void**)&p_pC, g_pC);
    cudaGetSymbolAddress((void**)&p_plvw, g_plvw);
    cudaGetSymbolAddress((void**)&p_k2, g_k2);
    cudaGetSymbolAddress((void**)&p_lvw, g_lvw);
    cudaGetSymbolAddress((void**)&p_sb, g_step_base);
    cudaGetSymbolAddress((void**)&p_qb2p, g_qb2p);
    cudaGetSymbolAddress((void**)&p_bhp, g_bhp);
    cudaGetSymbolAddress((void**)&p_qb2, g_qb2);
    cudaGetSymbolAddress((void**)&p_bh, g_bh);

    const float inv_sqrt_d = 0.03125f;
    const int S = Bn * Ln * Dn;

    // step_base (batch-independent)
    k_stepbase<<<(pl * Dn + 255) / 256, 256>>>(qpos, ptbl, pl);

    // qeff = (latents @ lat_q_w) @ ctx_k_w^T / sqrt(D)  (split-K x8 thin GEMMs)
    k_gemm<<<dim3(16, 1, 8), 256>>>(lats, lat_q_w, p_t1p, Ln, Dn, Dn, 0, nullptr, 1.f, 1, 0);
    k_gemm<<<dim3(16, 1, 8), 256>>>(p_t1p, ctx_k_w, p_qeffp, Ln, Dn, Dn, 1, nullptr, inv_sqrt_d, 8, Ln * Dn);
    k_redN<<<8, 256>>>((float4*)p_qeff, (const float4*)p_qeffp, Ln * Dn / 4, 8, Ln * Dn / 4);

    // stage-1 attention over ctx
    k_scores1<<<dim3(Tn / 32, Bn), 256>>>(ctx);
    k_softmax1<<<Bn * Ln, 256>>>();
    k_upart<<<dim3(2, 8, Bn), 128>>>(ctx);

    // chain of [256,1024]x[1024,1024] GEMMs (split-K x4, partials summed by consumers)
    k_gemm<<<dim3(16, 4, 4), 256>>>(p_up,  ctx_v_w,    p_pA,   Bn * Ln, Dn, Dn, 0, nullptr, 1.f, 8, S);
    k_gemm<<<dim3(16, 4, 4), 256>>>(p_pA,  lat_out_w,  p_pLC,  Bn * Ln, Dn, Dn, 0, nullptr, 1.f, 4, S);
    k_gemm<<<dim3(16, 4, 4), 256>>>(p_pLC, lat_k_w,    p_pk2,  Bn * Ln, Dn, Dn, 0, nullptr, 1.f, 4, S);
    k_gemm<<<dim3(16, 4, 4), 256>>>(p_pLC, lat_v_w,    p_pB,   Bn * Ln, Dn, Dn, 0, nullptr, 1.f, 4, S);
    k_gemm<<<dim3(16, 4, 4), 256>>>(p_pB,  step_out_w, p_pC,   Bn * Ln, Dn, Dn, 0, nullptr, 1.f, 4, S);
    k_gemm<<<dim3(16, 4, 4), 256>>>(p_pC,  gate_w1 + (size_t)Dn * Dn, p_plvw, Bn * Ln, Dn, Dn, 0, nullptr, 1.f, 4, S);
    k_redN<<<S / 4 / 256, 256>>>((float4*)p_k2,  (const float4*)p_pk2,  S / 4, 4, S / 4);
    k_redN<<<S / 4 / 256, 256>>>((float4*)p_lvw, (const float4*)p_plvw, S / 4, 4, S / 4);

    // batch-independent [P,D] GEMMs (split-K x2)
    int gy = (pl + 63) / 64;
    int n4p = pl * Dn / 4;
    k_gemm<<<dim3(16, gy, 2), 256>>>(p_sb, step_q_w, p_qb2p, pl, Dn, Dn, 0, nullptr, inv_sqrt_d, 1, 0);
    k_gemm<<<dim3(16, gy, 2), 256>>>(p_sb, gate_w1,  p_bhp,  pl, Dn, Dn, 0, nullptr, 1.f, 1, 0);
    k_redN<<<(n4p + 255) / 256, 256>>>((float4*)p_qb2, (const float4*)p_qb2p, n4p, 2, n4p);
    k_redN<<<(n4p + 255) / 256, 256>>>((float4*)p_bh,  (const float4*)p_bhp,  n4p, 2, n4p);

    // stage-2 attention weights
    k_s2<<<dim3((pl + 15) / 16, Bn), 256>>>(pl);

    // fused gate + top2 + combine
    const int smem_final = (Ln * Dn + 16 * 1026 + Dn + 64 + 272 + 16 + 4) * 4;
    cudaFuncSetAttribute(k_final, cudaFuncAttributeMaxDynamicSharedMemorySize, smem_final);
    k_final<<<dim3((pl + 7) / 8, Bn), 256, smem_final>>>(gate_w2, gate_b2, gate_b1, qexp, out, pl, Pfull);
}

// round 4
// speedup vs baseline: 1.4365x; 1.0021x over previous
#include <cuda_runtime.h>
#include <math.h>
#include <stdint.h>

#define Bn 32
#define Tn 2048
#define Dn 1024
#define En 16
#define Ln 8
#define Pmax 720
#define TSEG 64
#define NSEG (Tn / TSEG)   // 32

typedef unsigned long long ull;

__device__ __forceinline__ void fma2(ull& d, ull a, ull b) {
    asm("fma.rn.f32x2 %0, %1, %2, %0;" : "+l"(d) : "l"(a), "l"(b));
}
__device__ __forceinline__ float2 u2f(ull v) {
    float2 f; asm("mov.b64 {%0,%1}, %2;" : "=f"(f.x), "=f"(f.y) : "l"(v)); return f;
}
__device__ __forceinline__ float gelu_f(float x) {
    return 0.5f * x * (1.0f + erff(x * 0.70710678118654752440f));
}

// ---------------- scratch ----------------
__device__ float g_step_base[Pmax * Dn];
__device__ float g_t1p[8 * Ln * Dn];
__device__ float g_qeffp[8 * Ln * Dn];
__device__ float g_qeff[Ln * Dn];
__device__ float g_ssum[Bn * Ln * NSEG];
__device__ float g_upart[(size_t)NSEG * Bn * Ln * Dn];  // 33.5MB
__device__ float g_U[Bn * Ln * Dn];
__device__ float g_pA[4 * Bn * Ln * Dn];
__device__ float g_pLC[4 * Bn * Ln * Dn];
__device__ float g_pk2[4 * Bn * Ln * Dn];
__device__ float g_pB[4 * Bn * Ln * Dn];
__device__ float g_pC[4 * Bn * Ln * Dn];
__device__ float g_plvw[4 * Bn * Ln * Dn];
__device__ float g_k2[Bn * Ln * Dn];
__device__ float g_lvw[Bn * Ln * Dn];
__device__ float g_qb2p[2 * Pmax * Dn];
__device__ float g_bhp[2 * Pmax * Dn];
__device__ float g_qb2[Pmax * Dn];
__device__ float g_bh[Pmax * Dn];
__device__ float g_A2[Bn * Pmax * Ln];
__device__ float4 g_sel[Bn * Pmax];

// ---------------- step_base ----------------
__global__ void k_stepbase(const float* __restrict__ qpos,
                           const float* __restrict__ tbl, int pl) {
    int i = blockIdx.x * 256 + threadIdx.x;
    if (i < pl * Dn)
        g_step_base[i] = qpos[i] + tbl[(size_t)pl * Dn + (i & (Dn - 1))];
}

// ---------------- split-K fp32x2 GEMM ----------------
#define GEMM_PREFETCH(k0)                                                        \
    {                                                                            \
        for (int r = 0; r < 4; r++) {                                            \
            int i = tid + 256 * r;                                               \
            int row = i >> 4, col = i & 15;                                      \
            int gm = m0 + row;                                                   \
            float v = 0.f;                                                       \
            if (gm < M) {                                                        \
                size_t off = (size_t)gm * K + (k0) + col;                        \
                v = A[off];                                                      \
                for (int s = 1; s < nsumA; s++) v += A[off + (size_t)s * strideA]; \
            }                                                                    \
            ra[r] = v;                                                           \
        }                                                                        \
        if (!transB) {                                                           \
            for (int r = 0; r < 4; r++) {                                        \
                int i = tid + 256 * r;                                           \
                rb[r] = B[(size_t)((k0) + (i >> 6)) * N + n0 + (i & 63)];        \
            }                                                                    \
        } else {                                                                 \
            for (int r = 0; r < 4; r++) {                                        \
                int i = tid + 256 * r;                                           \
                rb[r] = B[(size_t)(n0 + (i >> 4)) * K + (k0) + (i & 15)];        \
            }                                                                    \
        }                                                                        \
    }

#define GEMM_STORE(bf)                                                           \
    {                                                                            \
        for (int r = 0; r < 4; r++) {                                            \
            int i = tid + 256 * r;                                               \
            *(float2*)&As2[bf][i & 15][2 * (i >> 4)] = make_float2(ra[r], ra[r]); \
        }                                                                        \
        if (!transB) {                                                           \
            for (int r = 0; r < 4; r++) {                                        \
                int i = tid + 256 * r;                                           \
                Bs[bf][i >> 6][i & 63] = rb[r];                                  \
            }                                                                    \
        } else {                                                                 \
            for (int r = 0; r < 4; r++) {                                        \
                int i = tid + 256 * r;                                           \
                Bs[bf][i & 15][i >> 4] = rb[r];                                  \
            }                                                                    \
        }                                                                        \
    }

#define GEMM_COMPUTE(bf)                                                         \
    {                                                                            \
        _Pragma("unroll")                                                        \
        for (int kk = 0; kk < 16; kk++) {                                        \
            ulonglong2 a01 = *(const ulonglong2*)&As2[bf][kk][ty * 8];           \
            ulonglong2 a23 = *(const ulonglong2*)&As2[bf][kk][ty * 8 + 4];       \
            ulonglong2 bb  = *(const ulonglong2*)&Bs[bf][kk][tx * 4];            \
            fma2(acc[0][0], a01.x, bb.x); fma2(acc[0][1], a01.x, bb.y);          \
            fma2(acc[1][0], a01.y, bb.x); fma2(acc[1][1], a01.y, bb.y);          \
            fma2(acc[2][0], a23.x, bb.x); fma2(acc[2][1], a23.x, bb.y);          \
            fma2(acc[3][0], a23.y, bb.x); fma2(acc[3][1], a23.y, bb.y);          \
        }                                                                        \
    }

__global__ void k_gemm(const float* __restrict__ A, const float* __restrict__ B,
                       float* __restrict__ C, int M, int N, int K,
                       int transB, const float* __restrict__ bias, float alpha,
                       int nsumA, int strideA) {
    __shared__ float As2[2][16][136];
    __shared__ float Bs[2][16][68];
    int tid = threadIdx.x;
    int tx = tid & 15, ty = tid >> 4;
    int m0 = blockIdx.y * 64, n0 = blockIdx.x * 64;
    int kper = K / gridDim.z;
    int kbeg = blockIdx.z * kper;
    C += (size_t)blockIdx.z * M * N;
    int nk = kper / 16;

    ull acc[4][2];
#pragma unroll
    for (int i = 0; i < 4; i++) { acc[i][0] = 0ULL; acc[i][1] = 0ULL; }

    float ra[4], rb[4];
    int buf = 0;
    GEMM_PREFETCH(kbeg);
    GEMM_STORE(0);
    __syncthreads();
    for (int kt = 0; kt < nk; kt++) {
        if (kt + 1 < nk) GEMM_PREFETCH(kbeg + (kt + 1) * 16);
        GEMM_COMPUTE(buf);
        if (kt + 1 < nk) {
            GEMM_STORE(buf ^ 1);
            __syncthreads();
            buf ^= 1;
        }
    }
#pragma unroll
    for (int i = 0; i < 4; i++) {
        int m = m0 + ty * 4 + i;
        if (m >= M) continue;
        float2 p0 = u2f(acc[i][0]), p1 = u2f(acc[i][1]);
        float4 o;
        o.x = alpha * p0.x; o.y = alpha * p0.y;
        o.z = alpha * p1.x; o.w = alpha * p1.y;
        if (bias) {
            o.x += bias[n0 + tx * 4];     o.y += bias[n0 + tx * 4 + 1];
            o.z += bias[n0 + tx * 4 + 2]; o.w += bias[n0 + tx * 4 + 3];
        }
        *(float4*)&C[(size_t)m * N + n0 + tx * 4] = o;
    }
}

// ---------------- generic partial reduction ----------------
__global__ void k_redN(float4* __restrict__ dst, const float4* __restrict__ src,
                       int n4, int nparts, int stride4) {
    int i = blockIdx.x * 256 + threadIdx.x;
    if (i >= n4) return;
    float4 s = src[i];
    for (int p = 1; p < nparts; p++) {
        float4 t = src[i + (size_t)p * stride4];
        s.x += t.x; s.y += t.y; s.z += t.z; s.w += t.w;
    }
    dst[i] = s;
}

// ---------------- fused stage-1: scores -> exp (no max) -> partial sums+U --------
// grid (NSEG, Bn), 256 threads. Block owns 64 tokens of one batch.
__global__ void k_fused1(const float* __restrict__ ctx) {
    __shared__ float qs[Ln][Dn];         // 32KB
    __shared__ float ps2[Ln][2 * TSEG];  // exp probs, duplicated for f32x2
    int tid = threadIdx.x;
    for (int i = tid; i < Ln * Dn / 4; i += 256)
        ((float4*)qs)[i] = ((const float4*)g_qeff)[i];
    __syncthreads();
    int b = blockIdx.y, seg = blockIdx.x;
    int w = tid >> 5, lane = tid & 31;
    int t0 = seg * TSEG;

    // phase A: scores + exp, 4 rows per warp per pass, 2 passes
    for (int pass = 0; pass < 2; pass++) {
        int tb = w * 8 + pass * 4;
        const float* base = ctx + ((size_t)b * Tn + t0 + tb) * Dn;
        ull acc[4][Ln];
#pragma unroll
        for (int tt = 0; tt < 4; tt++)
#pragma unroll
            for (int l = 0; l < Ln; l++) acc[tt][l] = 0ULL;
#pragma unroll
        for (int i = 0; i < 8; i++) {
            int d = (lane + 32 * i) * 4;
            ulonglong2 c0 = *(const ulonglong2*)(base + d);
            ulonglong2 c1 = *(const ulonglong2*)(base + Dn + d);
            ulonglong2 c2 = *(const ulonglong2*)(base + 2 * Dn + d);
            ulonglong2 c3 = *(const ulonglong2*)(base + 3 * Dn + d);
#pragma unroll
            for (int l = 0; l < Ln; l++) {
                ulonglong2 q = *(const ulonglong2*)&qs[l][d];
                fma2(acc[0][l], c0.x, q.x); fma2(acc[0][l], c0.y, q.y);
                fma2(acc[1][l], c1.x, q.x); fma2(acc[1][l], c1.y, q.y);
                fma2(acc[2][l], c2.x, q.x); fma2(acc[2][l], c2.y, q.y);
                fma2(acc[3][l], c3.x, q.x); fma2(acc[3][l], c3.y, q.y);
            }
        }
#pragma unroll
        for (int tt = 0; tt < 4; tt++)
#pragma unroll
            for (int l = 0; l < Ln; l++) {
                float2 f = u2f(acc[tt][l]);
                float v = f.x + f.y;
                for (int off = 16; off; off >>= 1)
                    v += __shfl_xor_sync(0xffffffffu, v, off);
                if (lane == 0) {
                    float e = expf(fminf(v, 60.0f));  // shift-free softmax (scores tiny)
                    ps2[l][2 * (tb + tt)] = e;
                    ps2[l][2 * (tb + tt) + 1] = e;
                }
            }
    }
    __syncthreads();

    // phase B: per-l partial sum of exps (warp l)
    {
        float s = ps2[w][4 * lane] + ps2[w][4 * lane + 2];
        for (int off = 16; off; off >>= 1)
            s += __shfl_xor_sync(0xffffffffu, s, off);
        if (lane == 0) g_ssum[((size_t)b * Ln + w) * NSEG + seg] = s;
    }

    // phase C: partial U = exp-probs @ ctx (tile should be L2-hot)
    int d = tid * 4;
    ull acc[Ln][2];
#pragma unroll
    for (int l = 0; l < Ln; l++) { acc[l][0] = 0ULL; acc[l][1] = 0ULL; }
    const float* cb = ctx + ((size_t)b * Tn + t0) * Dn + d;
#pragma unroll 4
    for (int tt = 0; tt < TSEG; tt++) {
        ulonglong2 c = *(const ulonglong2*)(cb + (size_t)tt * Dn);
#pragma unroll
        for (int l = 0; l < Ln; l++) {
            ull p = *(const ull*)&ps2[l][2 * tt];
            fma2(acc[l][0], p, c.x);
            fma2(acc[l][1], p, c.y);
        }
    }
#pragma unroll
    for (int l = 0; l < Ln; l++) {
        float2 f0 = u2f(acc[l][0]), f1 = u2f(acc[l][1]);
        *(float4*)&g_upart[(((size_t)seg * Bn + b) * Ln + l) * Dn + d] =
            make_float4(f0.x, f0.y, f1.x, f1.y);
    }
}

// ---------------- combine stage-1 partials: U = sum(upart)/sum(exp) --------------
// grid (4, Bn), 256 threads; thread owns one d (scalar, coalesced)
__global__ void k_comb1() {
    __shared__ float inv[Ln];
    int b = blockIdx.y, dc = blockIdx.x;
    int tid = threadIdx.x;
    if (tid < Ln) {
        float s0 = 0.f, s1 = 0.f, s2 = 0.f, s3 = 0.f;
#pragma unroll
        for (int g = 0; g < NSEG; g += 4) {
            s0 += g_ssum[((size_t)b * Ln + tid) * NSEG + g];
            s1 += g_ssum[((size_t)b * Ln + tid) * NSEG + g + 1];
            s2 += g_ssum[((size_t)b * Ln + tid) * NSEG + g + 2];
            s3 += g_ssum[((size_t)b * Ln + tid) * NSEG + g + 3];
        }
        inv[tid] = 1.0f / ((s0 + s1) + (s2 + s3));
    }
    __syncthreads();
    int dg = dc * 256 + tid;
#pragma unroll
    for (int l = 0; l < Ln; l++) {
        float a0 = 0.f, a1 = 0.f, a2 = 0.f, a3 = 0.f;
#pragma unroll
        for (int s = 0; s < NSEG; s += 4) {
            a0 += g_upart[(((size_t)(s + 0) * Bn + b) * Ln + l) * Dn + dg];
            a1 += g_upart[(((size_t)(s + 1) * Bn + b) * Ln + l) * Dn + dg];
            a2 += g_upart[(((size_t)(s + 2) * Bn + b) * Ln + l) * Dn + dg];
            a3 += g_upart[(((size_t)(s + 3) * Bn + b) * Ln + l) * Dn + dg];
        }
        g_U[((size_t)b * Ln + l) * Dn + dg] = ((a0 + a1) + (a2 + a3)) * inv[l];
    }
}

// ---------------- stage-2 scores + softmax over L=8 ----------------
__global__ void k_s2(int pl) {
    __shared__ float ks[Ln][Dn];  // 32KB
    int tid = threadIdx.x, b = blockIdx.y;
    for (int i = tid; i < Ln * Dn / 4; i += 256)
        ((float4*)ks)[i] = ((const float4*)(g_k2 + (size_t)b * Ln * Dn))[i];
    __syncthreads();
    int w = tid >> 5, lane = tid & 31;
    int p0 = blockIdx.x * 16 + w * 2;
    if (p0 > pl - 2) p0 = pl - 2;
    ull acc[2][Ln];
#pragma unroll
    for (int pp = 0; pp < 2; pp++)
#pragma unroll
        for (int l = 0; l < Ln; l++) acc[pp][l] = 0ULL;
#pragma unroll
    for (int i = 0; i < 8; i++) {
        int d = (lane + 32 * i) * 4;
        ulonglong2 q0 = *(const ulonglong2*)(g_qb2 + (size_t)p0 * Dn + d);
        ulonglong2 q1 = *(const ulonglong2*)(g_qb2 + (size_t)(p0 + 1) * Dn + d);
#pragma unroll
        for (int l = 0; l < Ln; l++) {
            ulonglong2 k = *(const ulonglong2*)&ks[l][d];
            fma2(acc[0][l], q0.x, k.x); fma2(acc[0][l], q0.y, k.y);
            fma2(acc[1][l], q1.x, k.x); fma2(acc[1][l], q1.y, k.y);
        }
    }
#pragma unroll
    for (int pp = 0; pp < 2; pp++) {
        float v[Ln];
#pragma unroll
        for (int l = 0; l < Ln; l++) {
            float2 f = u2f(acc[pp][l]);
            float s = f.x + f.y;
            for (int off = 16; off; off >>= 1)
                s += __shfl_xor_sync(0xffffffffu, s, off);
            v[l] = s;
        }
        if (lane == 0) {
            int p = p0 + pp;
            if (p < pl) {
                float m = v[0];
#pragma unroll
                for (int l = 1; l < Ln; l++) m = fmaxf(m, v[l]);
                float e[Ln], s = 0.f;
#pragma unroll
                for (int l = 0; l < Ln; l++) { e[l] = expf(v[l] - m); s += e[l]; }
                float inv = 1.0f / s;
#pragma unroll
                for (int l = 0; l < Ln; l++)
                    g_A2[((size_t)b * pl + p) * Ln + l] = e[l] * inv;
            }
        }
    }
}

// ---------------- gate select: h = gelu(...), logits, top-2 -> g_sel -------------
__global__ void k_gatesel(const float* __restrict__ w2, const float* __restrict__ b2,
                          const float* __restrict__ b1, int pl) {
    extern __shared__ float sm[];
    float* lvws = sm;                    // 8192
    float* w2T  = lvws + Ln * Dn;        // 16*1026
    float* hs   = w2T + 16 * 1026;       // 1024
    float* a2s  = hs + Dn;               // 64
    float* part = a2s + 64;              // 272
    float* lg   = part + 272;            // 16
    int tid = threadIdx.x, b = blockIdx.y, p0 = blockIdx.x * 8;
    for (int i = tid; i < Ln * Dn / 4; i += 256)
        ((float4*)lvws)[i] = ((const float4*)(g_lvw + (size_t)b * Ln * Dn))[i];
    for (int i = tid; i < Dn * En; i += 256) {
        int d = i >> 4, e = i & 15;
        w2T[e * 1026 + d] = w2[i];
    }
    if (tid < 64) {
        int pi = tid >> 3, l = tid & 7;
        int p = p0 + pi;
        a2s[tid] = (p < pl) ? g_A2[((size_t)b * pl + p) * Ln + l] : 0.f;
    }
    // prefetch bh for all 8 p (hides latency across whole block)
    float4 bh4[8];
#pragma unroll
    for (int pi = 0; pi < 8; pi++) {
        int p = p0 + pi;
        bh4[pi] = (p < pl) ? *(const float4*)(g_bh + (size_t)p * Dn + tid * 4)
                           : make_float4(0, 0, 0, 0);
    }
    float4 b1v = *(const float4*)(b1 + tid * 4);
    __syncthreads();
    int e_id = tid & 15, dseg = tid >> 4;
    for (int pi = 0; pi < 8; pi++) {
        int p = p0 + pi;
        if (p >= pl) break;  // block-uniform
        float4 s4 = bh4[pi];
        s4.x += b1v.x; s4.y += b1v.y; s4.z += b1v.z; s4.w += b1v.w;
#pragma unroll
        for (int l = 0; l < Ln; l++) {
            float a = a2s[pi * 8 + l];
            float4 v = ((const float4*)lvws)[l * (Dn / 4) + tid];
            s4.x += a * v.x; s4.y += a * v.y; s4.z += a * v.z; s4.w += a * v.w;
        }
        float4 h4;
        h4.x = gelu_f(s4.x); h4.y = gelu_f(s4.y);
        h4.z = gelu_f(s4.z); h4.w = gelu_f(s4.w);
        ((float4*)hs)[tid] = h4;
        __syncthreads();
        ull lacc = 0ULL;
        int dbase = dseg * 64;
#pragma unroll
        for (int j = 0; j < 32; j++) {
            ull h2 = *(const ull*)&hs[dbase + 2 * j];
            ull wv = *(const ull*)&w2T[e_id * 1026 + dbase + 2 * j];
            fma2(lacc, h2, wv);
        }
        float2 lf = u2f(lacc);
        part[dseg * 17 + e_id] = lf.x + lf.y;
        __syncthreads();
        if (tid < En) {
            float L = b2[tid];
#pragma unroll
            for (int g = 0; g < 16; g++) L += part[g * 17 + tid];
            lg[tid] = L;
        }
        __syncthreads();
        if (tid == 0) {
            float b1s = lg[0]; int e1 = 0;
#pragma unroll
            for (int e = 1; e < En; e++) if (lg[e] > b1s) { b1s = lg[e]; e1 = e; }
            float b2s = -3.4e38f; int e2 = 0;
#pragma unroll
            for (int e = 0; e < En; e++)
                if (e != e1 && lg[e] > b2s) { b2s = lg[e]; e2 = e; }
            float x2 = expf(b2s - b1s);
            float s = 1.f + x2;
            g_sel[(size_t)b * pl + p] = make_float4(
                1.f / s, x2 / s, __int_as_float(e1), __int_as_float(e2));
        }
        __syncthreads();
    }
}

// ---------------- combine experts: out = wA*qexp[eA,p] + wB*qexp[eB,p] ----------
// grid (pl), 256 threads; all 32 batches share p -> qexp rows dedup in L2
__global__ void k_combine(const float* __restrict__ qexp, float* __restrict__ out,
                          int pl, int Pfull) {
    __shared__ float4 sel[Bn];
    int p = blockIdx.x, tid = threadIdx.x;
    if (tid < Bn) sel[tid] = g_sel[(size_t)tid * pl + p];
    __syncthreads();
#pragma unroll 4
    for (int b = 0; b < Bn; b++) {
        float4 s = sel[b];
        int eA = __float_as_int(s.z), eB = __float_as_int(s.w);
        float4 va = *(const float4*)(qexp + ((size_t)eA * Pfull + p) * Dn + tid * 4);
        float4 vb = *(const float4*)(qexp + ((size_t)eB * Pfull + p) * Dn + tid * 4);
        float4 o;
        o.x = s.x * va.x + s.y * vb.x;
        o.y = s.x * va.y + s.y * vb.y;
        o.z = s.x * va.z + s.y * vb.z;
        o.w = s.x * va.w + s.y * vb.w;
        *(float4*)(out + ((size_t)b * pl + p) * Dn + tid * 4) = o;
    }
}

// ---------------- launch ----------------
extern "C" void kernel_launch(void* const* d_in, const int* in_sizes, int n_in,
                              void* d_out, int out_size) {
    const float* ctx        = (const float*)d_in[0];
    const float* qexp       = (const float*)d_in[1];
    const float* qpos       = (const float*)d_in[2];
    const float* ptbl       = (const float*)d_in[3];
    const float* lats       = (const float*)d_in[4];
    const float* lat_q_w    = (const float*)d_in[5];
    const float* ctx_k_w    = (const float*)d_in[6];
    const float* ctx_v_w    = (const float*)d_in[7];
    const float* lat_out_w  = (const float*)d_in[8];
    const float* step_q_w   = (const float*)d_in[9];
    const float* lat_k_w    = (const float*)d_in[10];
    const float* lat_v_w    = (const float*)d_in[11];
    const float* step_out_w = (const float*)d_in[12];
    const float* gate_w1    = (const float*)d_in[13];
    const float* gate_b1    = (const float*)d_in[14];
    const float* gate_w2    = (const float*)d_in[15];
    const float* gate_b2    = (const float*)d_in[16];
    float* out = (float*)d_out;

    int pl = out_size / (Bn * Dn);
    int Pfull = in_sizes[2] / Dn;

    float *p_t1p, *p_qeffp, *p_qeff, *p_U;
    float *p_pA, *p_pLC, *p_pk2, *p_pB, *p_pC, *p_plvw;
    float *p_k2, *p_lvw, *p_sb, *p_qb2p, *p_bhp, *p_qb2, *p_bh;
    cudaGetSymbolAddress((void**)&p_t1p, g_t1p);
    cudaGetSymbolAddress((void**)&p_qeffp, g_qeffp);
    cudaGetSymbolAddress((void**)&p_qeff, g_qeff);
    cudaGetSymbolAddress((void**)&p_U, g_U);
    cudaGetSymbolAddress((void**)&p_pA, g_pA);
    cudaGetSymbolAddress((void**)&p_pLC, g_pLC);
    cudaGetSymbolAddress((void**)&p_pk2, g_pk2);
    cudaGetSymbolAddress((void**)&p_pB, g_pB);
    cudaGetSymbolAddress((void**)&p_pC, g_pC);
    cudaGetSymbolAddress((void**)&p_plvw, g_plvw);
    cudaGetSymbolAddress((void**)&p_k2, g_k2);
    cudaGetSymbolAddress((void**)&p_lvw, g_lvw);
    cudaGetSymbolAddress((void**)&p_sb, g_step_base);
    cudaGetSymbolAddress((void**)&p_qb2p, g_qb2p);
    cudaGetSymbolAddress((void**)&p_bhp, g_bhp);
    cudaGetSymbolAddress((void**)&p_qb2, g_qb2);
    cudaGetSymbolAddress((void**)&p_bh, g_bh);

    const float inv_sqrt_d = 0.03125f;
    const int S = Bn * Ln * Dn;

    // step_base (batch-independent)
    k_stepbase<<<(pl * Dn + 255) / 256, 256>>>(qpos, ptbl, pl);

    // qeff = (latents @ lat_q_w) @ ctx_k_w^T / sqrt(D)
    k_gemm<<<dim3(16, 1, 8), 256>>>(lats, lat_q_w, p_t1p, Ln, Dn, Dn, 0, nullptr, 1.f, 1, 0);
    k_gemm<<<dim3(16, 1, 8), 256>>>(p_t1p, ctx_k_w, p_qeffp, Ln, Dn, Dn, 1, nullptr, inv_sqrt_d, 8, Ln * Dn);
    k_redN<<<8, 256>>>((float4*)p_qeff, (const float4*)p_qeffp, Ln * Dn / 4, 8, Ln * Dn / 4);

    // fused stage-1 attention (single ctx pass + L2-hot second read)
    k_fused1<<<dim3(NSEG, Bn), 256>>>(ctx);
    k_comb1<<<dim3(4, Bn), 256>>>();

    // chain of [256,1024]x[1024,1024] GEMMs (split-K x4)
    k_gemm<<<dim3(16, 4, 4), 256>>>(p_U,   ctx_v_w,    p_pA,   Bn * Ln, Dn, Dn, 0, nullptr, 1.f, 1, 0);
    k_gemm<<<dim3(16, 4, 4), 256>>>(p_pA,  lat_out_w,  p_pLC,  Bn * Ln, Dn, Dn, 0, nullptr, 1.f, 4, S);
    k_gemm<<<dim3(16, 4, 4), 256>>>(p_pLC, lat_k_w,    p_pk2,  Bn * Ln, Dn, Dn, 0, nullptr, 1.f, 4, S);
    k_gemm<<<dim3(16, 4, 4), 256>>>(p_pLC, lat_v_w,    p_pB,   Bn * Ln, Dn, Dn, 0, nullptr, 1.f, 4, S);
    k_gemm<<<dim3(16, 4, 4), 256>>>(p_pB,  step_out_w, p_pC,   Bn * Ln, Dn, Dn, 0, nullptr, 1.f, 4, S);
    k_gemm<<<dim3(16, 4, 4), 256>>>(p_pC,  gate_w1 + (size_t)Dn * Dn, p_plvw, Bn * Ln, Dn, Dn, 0, nullptr, 1.f, 4, S);
    k_redN<<<S / 4 / 256, 256>>>((float4*)p_k2,  (const float4*)p_pk2,  S / 4, 4, S / 4);
    k_redN<<<S / 4 / 256, 256>>>((float4*)p_lvw, (const float4*)p_plvw, S / 4, 4, S / 4);

    // batch-independent [P,D] GEMMs (split-K x2)
    int gy = (pl + 63) / 64;
    int n4p = pl * Dn / 4;
    k_gemm<<<dim3(16, gy, 2), 256>>>(p_sb, step_q_w, p_qb2p, pl, Dn, Dn, 0, nullptr, inv_sqrt_d, 1, 0);
    k_gemm<<<dim3(16, gy, 2), 256>>>(p_sb, gate_w1,  p_bhp,  pl, Dn, Dn, 0, nullptr, 1.f, 1, 0);
    k_redN<<<(n4p + 255) / 256, 256>>>((float4*)p_qb2, (const float4*)p_qb2p, n4p, 2, n4p);
    k_redN<<<(n4p + 255) / 256, 256>>>((float4*)p_bh,  (const float4*)p_bhp,  n4p, 2, n4p);

    // stage-2 attention weights
    k_s2<<<dim3((pl + 15) / 16, Bn), 256>>>(pl);

    // gate select (logits + top2) then pure-streaming expert combine
    const int smem_gs = (Ln * Dn + 16 * 1026 + Dn + 64 + 272 + 16) * 4;
    cudaFuncSetAttribute(k_gatesel, cudaFuncAttributeMaxDynamicSharedMemorySize, smem_gs);
    k_gatesel<<<dim3((pl + 7) / 8, Bn), 256, smem_gs>>>(gate_w2, gate_b2, gate_b1, pl);
    k_combine<<<pl, 256>>>(qexp, out, pl, Pfull);
}

// round 5
// speedup vs baseline: 1.6462x; 1.1459x over previous
#include <cuda_runtime.h>
#include <math.h>
#include <stdint.h>

#define Bn 32
#define Tn 2048
#define Dn 1024
#define En 16
#define Ln 8
#define Pmax 720
#define SUBSEG 32          // tokens per sub-segment (smem tile)
#define NSUB 4             // sub-segments per block
#define NPART 16           // stage-1 partial count = Tn/(SUBSEG*NSUB)

typedef unsigned long long ull;

__device__ __forceinline__ void fma2(ull& d, ull a, ull b) {
    asm("fma.rn.f32x2 %0, %1, %2, %0;" : "+l"(d) : "l"(a), "l"(b));
}
__device__ __forceinline__ float2 u2f(ull v) {
    float2 f; asm("mov.b64 {%0,%1}, %2;" : "=f"(f.x), "=f"(f.y) : "l"(v)); return f;
}
__device__ __forceinline__ float gelu_f(float x) {
    return 0.5f * x * (1.0f + erff(x * 0.70710678118654752440f));
}

// ---------------- scratch ----------------
__device__ float g_step_base[Pmax * Dn];
__device__ float g_t1p[8 * Ln * Dn];
__device__ float g_qeffp[8 * Ln * Dn];
__device__ float g_qeff[Ln * Dn];
__device__ float g_ssum[Bn * Ln * NPART];
__device__ float g_upart[(size_t)NPART * Bn * Ln * Dn];  // 16.8MB
__device__ float g_U[Bn * Ln * Dn];
__device__ float g_pA[8 * Bn * Ln * Dn];
__device__ float g_pLC[8 * Bn * Ln * Dn];
__device__ float g_pk2[8 * Bn * Ln * Dn];
__device__ float g_pB[8 * Bn * Ln * Dn];
__device__ float g_pC[8 * Bn * Ln * Dn];
__device__ float g_plvw[8 * Bn * Ln * Dn];
__device__ float g_k2[Bn * Ln * Dn];
__device__ float g_lvw[Bn * Ln * Dn];
__device__ float g_qb2p[4 * Pmax * Dn];
__device__ float g_bhp[4 * Pmax * Dn];
__device__ float g_qb2[Pmax * Dn];
__device__ float g_bh[Pmax * Dn];
__device__ float g_A2[Bn * Pmax * Ln];
__device__ float4 g_sel[Bn * Pmax];

// ---------------- step_base ----------------
__global__ void k_stepbase(const float* __restrict__ qpos,
                           const float* __restrict__ tbl, int pl) {
    int i = blockIdx.x * 256 + threadIdx.x;
    if (i < pl * Dn)
        g_step_base[i] = qpos[i] + tbl[(size_t)pl * Dn + (i & (Dn - 1))];
}

// ---------------- split-K fp32x2 GEMM ----------------
#define GEMM_PREFETCH(k0)                                                        \
    {                                                                            \
        for (int r = 0; r < 4; r++) {                                            \
            int i = tid + 256 * r;                                               \
            int row = i >> 4, col = i & 15;                                      \
            int gm = m0 + row;                                                   \
            float v = 0.f;                                                       \
            if (gm < M) {                                                        \
                size_t off = (size_t)gm * K + (k0) + col;                        \
                v = A[off];                                                      \
                for (int s = 1; s < nsumA; s++) v += A[off + (size_t)s * strideA]; \
            }                                                                    \
            ra[r] = v;                                                           \
        }                                                                        \
        if (!transB) {                                                           \
            for (int r = 0; r < 4; r++) {                                        \
                int i = tid + 256 * r;                                           \
                rb[r] = B[(size_t)((k0) + (i >> 6)) * N + n0 + (i & 63)];        \
            }                                                                    \
        } else {                                                                 \
            for (int r = 0; r < 4; r++) {                                        \
                int i = tid + 256 * r;                                           \
                rb[r] = B[(size_t)(n0 + (i >> 4)) * K + (k0) + (i & 15)];        \
            }                                                                    \
        }                                                                        \
    }

#define GEMM_STORE(bf)                                                           \
    {                                                                            \
        for (int r = 0; r < 4; r++) {                                            \
            int i = tid + 256 * r;                                               \
            *(float2*)&As2[bf][i & 15][2 * (i >> 4)] = make_float2(ra[r], ra[r]); \
        }                                                                        \
        if (!transB) {                                                           \
            for (int r = 0; r < 4; r++) {                                        \
                int i = tid + 256 * r;                                           \
                Bs[bf][i >> 6][i & 63] = rb[r];                                  \
            }                                                                    \
        } else {                                                                 \
            for (int r = 0; r < 4; r++) {                                        \
                int i = tid + 256 * r;                                           \
                Bs[bf][i & 15][i >> 4] = rb[r];                                  \
            }                                                                    \
        }                                                                        \
    }

#define GEMM_COMPUTE(bf)                                                         \
    {                                                                            \
        _Pragma("unroll")                                                        \
        for (int kk = 0; kk < 16; kk++) {                                        \
            ulonglong2 a01 = *(const ulonglong2*)&As2[bf][kk][ty * 8];           \
            ulonglong2 a23 = *(const ulonglong2*)&As2[bf][kk][ty * 8 + 4];       \
            ulonglong2 bb  = *(const ulonglong2*)&Bs[bf][kk][tx * 4];            \
            fma2(acc[0][0], a01.x, bb.x); fma2(acc[0][1], a01.x, bb.y);          \
            fma2(acc[1][0], a01.y, bb.x); fma2(acc[1][1], a01.y, bb.y);          \
            fma2(acc[2][0], a23.x, bb.x); fma2(acc[2][1], a23.x, bb.y);          \
            fma2(acc[3][0], a23.y, bb.x); fma2(acc[3][1], a23.y, bb.y);          \
        }                                                                        \
    }

__global__ void k_gemm(const float* __restrict__ A, const float* __restrict__ B,
                       float* __restrict__ C, int M, int N, int K,
                       int transB, const float* __restrict__ bias, float alpha,
                       int nsumA, int strideA) {
    __shared__ float As2[2][16][136];
    __shared__ float Bs[2][16][68];
    int tid = threadIdx.x;
    int tx = tid & 15, ty = tid >> 4;
    int m0 = blockIdx.y * 64, n0 = blockIdx.x * 64;
    int kper = K / gridDim.z;
    int kbeg = blockIdx.z * kper;
    C += (size_t)blockIdx.z * M * N;
    int nk = kper / 16;

    ull acc[4][2];
#pragma unroll
    for (int i = 0; i < 4; i++) { acc[i][0] = 0ULL; acc[i][1] = 0ULL; }

    float ra[4], rb[4];
    int buf = 0;
    GEMM_PREFETCH(kbeg);
    GEMM_STORE(0);
    __syncthreads();
    for (int kt = 0; kt < nk; kt++) {
        if (kt + 1 < nk) GEMM_PREFETCH(kbeg + (kt + 1) * 16);
        GEMM_COMPUTE(buf);
        if (kt + 1 < nk) {
            GEMM_STORE(buf ^ 1);
            __syncthreads();
            buf ^= 1;
        }
    }
#pragma unroll
    for (int i = 0; i < 4; i++) {
        int m = m0 + ty * 4 + i;
        if (m >= M) continue;
        float2 p0 = u2f(acc[i][0]), p1 = u2f(acc[i][1]);
        float4 o;
        o.x = alpha * p0.x; o.y = alpha * p0.y;
        o.z = alpha * p1.x; o.w = alpha * p1.y;
        if (bias) {
            o.x += bias[n0 + tx * 4];     o.y += bias[n0 + tx * 4 + 1];
            o.z += bias[n0 + tx * 4 + 2]; o.w += bias[n0 + tx * 4 + 3];
        }
        *(float4*)&C[(size_t)m * N + n0 + tx * 4] = o;
    }
}

// ---------------- generic partial reduction ----------------
__global__ void k_redN(float4* __restrict__ dst, const float4* __restrict__ src,
                       int n4, int nparts, int stride4) {
    int i = blockIdx.x * 256 + threadIdx.x;
    if (i >= n4) return;
    float4 s = src[i];
    for (int p = 1; p < nparts; p++) {
        float4 t = src[i + (size_t)p * stride4];
        s.x += t.x; s.y += t.y; s.z += t.z; s.w += t.w;
    }
    dst[i] = s;
}

// ---------------- fused stage-1 (single DRAM pass over ctx) -----------------------
// grid (NPART=16, Bn), 256 threads, ~162KB dyn smem, 1 block/SM.
// Each block: 4 sub-segments of 32 tokens. Per sub-seg:
//   phase A: warp w loads 4 token rows (global, coalesced), stashes them in smem,
//            computes 8 scores each, exp -> ps2 (shift-free softmax).
//   phase C: U[l][d] += p[l][t] * ck[t][d]  entirely from smem.
__global__ void k_fused1(const float* __restrict__ ctx) {
    extern __shared__ float smf[];
    float* qs  = smf;                    // 8*1024   = 32KB
    float* ck  = qs + Ln * Dn;           // 32*1024  = 128KB
    float* ps2 = ck + SUBSEG * Dn;       // 8*64     = 2KB (dup pairs)
    int tid = threadIdx.x;
    for (int i = tid; i < Ln * Dn / 4; i += 256)
        ((float4*)qs)[i] = ((const float4*)g_qeff)[i];
    int b = blockIdx.y;
    int w = tid >> 5, lane = tid & 31;

    ull uacc[Ln][2];
#pragma unroll
    for (int l = 0; l < Ln; l++) { uacc[l][0] = 0ULL; uacc[l][1] = 0ULL; }
    float ssum = 0.f;  // warp w accumulates exp-sum for l = w

    for (int sub = 0; sub < NSUB; sub++) {
        int t0 = (blockIdx.x * NSUB + sub) * SUBSEG;
        const float* base = ctx + ((size_t)b * Tn + t0 + w * 4) * Dn;
        __syncthreads();  // previous phase C done before overwriting ck/ps2

        // phase A: 4 token rows per warp
        ull acc[4][Ln];
#pragma unroll
        for (int tt = 0; tt < 4; tt++)
#pragma unroll
            for (int l = 0; l < Ln; l++) acc[tt][l] = 0ULL;
#pragma unroll
        for (int i = 0; i < 8; i++) {
            int d = (lane + 32 * i) * 4;
            ulonglong2 c0 = *(const ulonglong2*)(base + d);
            ulonglong2 c1 = *(const ulonglong2*)(base + Dn + d);
            ulonglong2 c2 = *(const ulonglong2*)(base + 2 * Dn + d);
            ulonglong2 c3 = *(const ulonglong2*)(base + 3 * Dn + d);
            *(ulonglong2*)&ck[(w * 4 + 0) * Dn + d] = c0;
            *(ulonglong2*)&ck[(w * 4 + 1) * Dn + d] = c1;
            *(ulonglong2*)&ck[(w * 4 + 2) * Dn + d] = c2;
            *(ulonglong2*)&ck[(w * 4 + 3) * Dn + d] = c3;
#pragma unroll
            for (int l = 0; l < Ln; l++) {
                ulonglong2 q = *(const ulonglong2*)&qs[l * Dn + d];
                fma2(acc[0][l], c0.x, q.x); fma2(acc[0][l], c0.y, q.y);
                fma2(acc[1][l], c1.x, q.x); fma2(acc[1][l], c1.y, q.y);
                fma2(acc[2][l], c2.x, q.x); fma2(acc[2][l], c2.y, q.y);
                fma2(acc[3][l], c3.x, q.x); fma2(acc[3][l], c3.y, q.y);
            }
        }
#pragma unroll
        for (int tt = 0; tt < 4; tt++)
#pragma unroll
            for (int l = 0; l < Ln; l++) {
                float2 f = u2f(acc[tt][l]);
                float v = f.x + f.y;
                for (int off = 16; off; off >>= 1)
                    v += __shfl_xor_sync(0xffffffffu, v, off);
                if (lane == 0) {
                    float e = expf(fminf(v, 60.0f));  // shift-free softmax
                    ps2[l * 64 + 2 * (w * 4 + tt)] = e;
                    ps2[l * 64 + 2 * (w * 4 + tt) + 1] = e;
                }
            }
        __syncthreads();

        // phase B: exp-sum partial (warp w owns l = w; tt = lane)
        {
            float s = ps2[w * 64 + 2 * lane];
            for (int off = 16; off; off >>= 1)
                s += __shfl_xor_sync(0xffffffffu, s, off);
            ssum += s;
        }

        // phase C: U accumulation from smem
        int d = tid * 4;
#pragma unroll 4
        for (int tt = 0; tt < SUBSEG; tt++) {
            ulonglong2 c = *(const ulonglong2*)&ck[tt * Dn + d];
#pragma unroll
            for (int l = 0; l < Ln; l++) {
                ull p = *(const ull*)&ps2[l * 64 + 2 * tt];
                fma2(uacc[l][0], p, c.x);
                fma2(uacc[l][1], p, c.y);
            }
        }
    }
#pragma unroll
    for (int l = 0; l < Ln; l++) {
        float2 f0 = u2f(uacc[l][0]), f1 = u2f(uacc[l][1]);
        *(float4*)&g_upart[(((size_t)blockIdx.x * Bn + b) * Ln + l) * Dn + tid * 4] =
            make_float4(f0.x, f0.y, f1.x, f1.y);
    }
    if (lane == 0)
        g_ssum[((size_t)b * Ln + w) * NPART + blockIdx.x] = ssum;
}

// ---------------- combine stage-1 partials: U = sum(upart)/sum(exp) --------------
__global__ void k_comb1() {
    __shared__ float inv[Ln];
    int b = blockIdx.y, dc = blockIdx.x;
    int tid = threadIdx.x;
    if (tid < Ln) {
        float s0 = 0.f, s1 = 0.f, s2 = 0.f, s3 = 0.f;
#pragma unroll
        for (int g = 0; g < NPART; g += 4) {
            s0 += g_ssum[((size_t)b * Ln + tid) * NPART + g];
            s1 += g_ssum[((size_t)b * Ln + tid) * NPART + g + 1];
            s2 += g_ssum[((size_t)b * Ln + tid) * NPART + g + 2];
            s3 += g_ssum[((size_t)b * Ln + tid) * NPART + g + 3];
        }
        inv[tid] = 1.0f / ((s0 + s1) + (s2 + s3));
    }
    __syncthreads();
    int dg = dc * 256 + tid;
#pragma unroll
    for (int l = 0; l < Ln; l++) {
        float a0 = 0.f, a1 = 0.f, a2 = 0.f, a3 = 0.f;
#pragma unroll
        for (int s = 0; s < NPART; s += 4) {
            a0 += g_upart[(((size_t)(s + 0) * Bn + b) * Ln + l) * Dn + dg];
            a1 += g_upart[(((size_t)(s + 1) * Bn + b) * Ln + l) * Dn + dg];
            a2 += g_upart[(((size_t)(s + 2) * Bn + b) * Ln + l) * Dn + dg];
            a3 += g_upart[(((size_t)(s + 3) * Bn + b) * Ln + l) * Dn + dg];
        }
        g_U[((size_t)b * Ln + l) * Dn + dg] = ((a0 + a1) + (a2 + a3)) * inv[l];
    }
}

// ---------------- stage-2 scores + softmax over L=8 ----------------
__global__ void k_s2(int pl) {
    __shared__ float ks[Ln][Dn];  // 32KB
    int tid = threadIdx.x, b = blockIdx.y;
    for (int i = tid; i < Ln * Dn / 4; i += 256)
        ((float4*)ks)[i] = ((const float4*)(g_k2 + (size_t)b * Ln * Dn))[i];
    __syncthreads();
    int w = tid >> 5, lane = tid & 31;
    int p0 = blockIdx.x * 16 + w * 2;
    if (p0 > pl - 2) p0 = pl - 2;
    ull acc[2][Ln];
#pragma unroll
    for (int pp = 0; pp < 2; pp++)
#pragma unroll
        for (int l = 0; l < Ln; l++) acc[pp][l] = 0ULL;
#pragma unroll
    for (int i = 0; i < 8; i++) {
        int d = (lane + 32 * i) * 4;
        ulonglong2 q0 = *(const ulonglong2*)(g_qb2 + (size_t)p0 * Dn + d);
        ulonglong2 q1 = *(const ulonglong2*)(g_qb2 + (size_t)(p0 + 1) * Dn + d);
#pragma unroll
        for (int l = 0; l < Ln; l++) {
            ulonglong2 k = *(const ulonglong2*)&ks[l][d];
            fma2(acc[0][l], q0.x, k.x); fma2(acc[0][l], q0.y, k.y);
            fma2(acc[1][l], q1.x, k.x); fma2(acc[1][l], q1.y, k.y);
        }
    }
#pragma unroll
    for (int pp = 0; pp < 2; pp++) {
        float v[Ln];
#pragma unroll
        for (int l = 0; l < Ln; l++) {
            float2 f = u2f(acc[pp][l]);
            float s = f.x + f.y;
            for (int off = 16; off; off >>= 1)
                s += __shfl_xor_sync(0xffffffffu, s, off);
            v[l] = s;
        }
        if (lane == 0) {
            int p = p0 + pp;
            if (p < pl) {
                float m = v[0];
#pragma unroll
                for (int l = 1; l < Ln; l++) m = fmaxf(m, v[l]);
                float e[Ln], s = 0.f;
#pragma unroll
                for (int l = 0; l < Ln; l++) { e[l] = expf(v[l] - m); s += e[l]; }
                float inv = 1.0f / s;
#pragma unroll
                for (int l = 0; l < Ln; l++)
                    g_A2[((size_t)b * pl + p) * Ln + l] = e[l] * inv;
            }
        }
    }
}

// ---------------- gate select: h = gelu(...), logits, top-2 -> g_sel -------------
__global__ void k_gatesel(const float* __restrict__ w2, const float* __restrict__ b2,
                          const float* __restrict__ b1, int pl) {
    extern __shared__ float sm[];
    float* lvws = sm;                    // 8192
    float* w2T  = lvws + Ln * Dn;        // 16*1026
    float* hs   = w2T + 16 * 1026;       // 1024
    float* a2s  = hs + Dn;               // 64
    float* part = a2s + 64;              // 272
    float* lg   = part + 272;            // 16
    int tid = threadIdx.x, b = blockIdx.y, p0 = blockIdx.x * 8;
    for (int i = tid; i < Ln * Dn / 4; i += 256)
        ((float4*)lvws)[i] = ((const float4*)(g_lvw + (size_t)b * Ln * Dn))[i];
    for (int i = tid; i < Dn * En; i += 256) {
        int d = i >> 4, e = i & 15;
        w2T[e * 1026 + d] = w2[i];
    }
    if (tid < 64) {
        int pi = tid >> 3, l = tid & 7;
        int p = p0 + pi;
        a2s[tid] = (p < pl) ? g_A2[((size_t)b * pl + p) * Ln + l] : 0.f;
    }
    float4 bh4[8];
#pragma unroll
    for (int pi = 0; pi < 8; pi++) {
        int p = p0 + pi;
        bh4[pi] = (p < pl) ? *(const float4*)(g_bh + (size_t)p * Dn + tid * 4)
                           : make_float4(0, 0, 0, 0);
    }
    float4 b1v = *(const float4*)(b1 + tid * 4);
    __syncthreads();
    int e_id = tid & 15, dseg = tid >> 4;
    for (int pi = 0; pi < 8; pi++) {
        int p = p0 + pi;
        if (p >= pl) break;  // block-uniform
        float4 s4 = bh4[pi];
        s4.x += b1v.x; s4.y += b1v.y; s4.z += b1v.z; s4.w += b1v.w;
#pragma unroll
        for (int l = 0; l < Ln; l++) {
            float a = a2s[pi * 8 + l];
            float4 v = ((const float4*)lvws)[l * (Dn / 4) + tid];
            s4.x += a * v.x; s4.y += a * v.y; s4.z += a * v.z; s4.w += a * v.w;
        }
        float4 h4;
        h4.x = gelu_f(s4.x); h4.y = gelu_f(s4.y);
        h4.z = gelu_f(s4.z); h4.w = gelu_f(s4.w);
        ((float4*)hs)[tid] = h4;
        __syncthreads();
        ull lacc = 0ULL;
        int dbase = dseg * 64;
#pragma unroll
        for (int j = 0; j < 32; j++) {
            ull h2 = *(const ull*)&hs[dbase + 2 * j];
            ull wv = *(const ull*)&w2T[e_id * 1026 + dbase + 2 * j];
            fma2(lacc, h2, wv);
        }
        float2 lf = u2f(lacc);
        part[dseg * 17 + e_id] = lf.x + lf.y;
        __syncthreads();
        if (tid < En) {
            float L = b2[tid];
#pragma unroll
            for (int g = 0; g < 16; g++) L += part[g * 17 + tid];
            lg[tid] = L;
        }
        __syncthreads();
        if (tid == 0) {
            float b1s = lg[0]; int e1 = 0;
#pragma unroll
            for (int e = 1; e < En; e++) if (lg[e] > b1s) { b1s = lg[e]; e1 = e; }
            float b2s = -3.4e38f; int e2 = 0;
#pragma unroll
            for (int e = 0; e < En; e++)
                if (e != e1 && lg[e] > b2s) { b2s = lg[e]; e2 = e; }
            float x2 = expf(b2s - b1s);
            float s = 1.f + x2;
            g_sel[(size_t)b * pl + p] = make_float4(
                1.f / s, x2 / s, __int_as_float(e1), __int_as_float(e2));
        }
        __syncthreads();
    }
}

// ---------------- combine experts ----------------
__global__ void k_combine(const float* __restrict__ qexp, float* __restrict__ out,
                          int pl, int Pfull) {
    __shared__ float4 sel[Bn];
    int p = blockIdx.x, tid = threadIdx.x;
    if (tid < Bn) sel[tid] = g_sel[(size_t)tid * pl + p];
    __syncthreads();
#pragma unroll 4
    for (int b = 0; b < Bn; b++) {
        float4 s = sel[b];
        int eA = __float_as_int(s.z), eB = __float_as_int(s.w);
        float4 va = *(const float4*)(qexp + ((size_t)eA * Pfull + p) * Dn + tid * 4);
        float4 vb = *(const float4*)(qexp + ((size_t)eB * Pfull + p) * Dn + tid * 4);
        float4 o;
        o.x = s.x * va.x + s.y * vb.x;
        o.y = s.x * va.y + s.y * vb.y;
        o.z = s.x * va.z + s.y * vb.z;
        o.w = s.x * va.w + s.y * vb.w;
        *(float4*)(out + ((size_t)b * pl + p) * Dn + tid * 4) = o;
    }
}

// ---------------- launch ----------------
extern "C" void kernel_launch(void* const* d_in, const int* in_sizes, int n_in,
                              void* d_out, int out_size) {
    const float* ctx        = (const float*)d_in[0];
    const float* qexp       = (const float*)d_in[1];
    const float* qpos       = (const float*)d_in[2];
    const float* ptbl       = (const float*)d_in[3];
    const float* lats       = (const float*)d_in[4];
    const float* lat_q_w    = (const float*)d_in[5];
    const float* ctx_k_w    = (const float*)d_in[6];
    const float* ctx_v_w    = (const float*)d_in[7];
    const float* lat_out_w  = (const float*)d_in[8];
    const float* step_q_w   = (const float*)d_in[9];
    const float* lat_k_w    = (const float*)d_in[10];
    const float* lat_v_w    = (const float*)d_in[11];
    const float* step_out_w = (const float*)d_in[12];
    const float* gate_w1    = (const float*)d_in[13];
    const float* gate_b1    = (const float*)d_in[14];
    const float* gate_w2    = (const float*)d_in[15];
    const float* gate_b2    = (const float*)d_in[16];
    float* out = (float*)d_out;

    int pl = out_size / (Bn * Dn);
    int Pfull = in_sizes[2] / Dn;

    float *p_t1p, *p_qeffp, *p_qeff, *p_U;
    float *p_pA, *p_pLC, *p_pk2, *p_pB, *p_pC, *p_plvw;
    float *p_k2, *p_lvw, *p_sb, *p_qb2p, *p_bhp, *p_qb2, *p_bh;
    cudaGetSymbolAddress((void**)&p_t1p, g_t1p);
    cudaGetSymbolAddress((void**)&p_qeffp, g_qeffp);
    cudaGetSymbolAddress((void**)&p_qeff, g_qeff);
    cudaGetSymbolAddress((void**)&p_U, g_U);
    cudaGetSymbolAddress((void**)&p_pA, g_pA);
    cudaGetSymbolAddress((void**)&p_pLC, g_pLC);
    cudaGetSymbolAddress((void**)&p_pk2, g_pk2);
    cudaGetSymbolAddress((void**)&p_pB, g_pB);
    cudaGetSymbolAddress((void**)&p_pC, g_pC);
    cudaGetSymbolAddress((void**)&p_plvw, g_plvw);
    cudaGetSymbolAddress((void**)&p_k2, g_k2);
    cudaGetSymbolAddress((void**)&p_lvw, g_lvw);
    cudaGetSymbolAddress((void**)&p_sb, g_step_base);
    cudaGetSymbolAddress((void**)&p_qb2p, g_qb2p);
    cudaGetSymbolAddress((void**)&p_bhp, g_bhp);
    cudaGetSymbolAddress((void**)&p_qb2, g_qb2);
    cudaGetSymbolAddress((void**)&p_bh, g_bh);

    const float inv_sqrt_d = 0.03125f;
    const int S = Bn * Ln * Dn;

    // launches 0-2: qeff = (latents @ lat_q_w) @ ctx_k_w^T / sqrt(D)
    k_gemm<<<dim3(16, 1, 8), 256>>>(lats, lat_q_w, p_t1p, Ln, Dn, Dn, 0, nullptr, 1.f, 1, 0);
    k_gemm<<<dim3(16, 1, 8), 256>>>(p_t1p, ctx_k_w, p_qeffp, Ln, Dn, Dn, 1, nullptr, inv_sqrt_d, 8, Ln * Dn);
    k_redN<<<8, 256>>>((float4*)p_qeff, (const float4*)p_qeffp, Ln * Dn / 4, 8, Ln * Dn / 4);

    // launch 3 (ncu-sampled slot): fused stage-1, single DRAM pass over ctx
    const int smem_f1 = (Ln * Dn + SUBSEG * Dn + Ln * 64) * 4;
    cudaFuncSetAttribute(k_fused1, cudaFuncAttributeMaxDynamicSharedMemorySize, smem_f1);
    k_fused1<<<dim3(NPART, Bn), 256, smem_f1>>>(ctx);
    k_comb1<<<dim3(4, Bn), 256>>>();

    // chain of [256,1024]x[1024,1024] GEMMs (split-K x8)
    k_gemm<<<dim3(16, 4, 8), 256>>>(p_U,   ctx_v_w,    p_pA,   Bn * Ln, Dn, Dn, 0, nullptr, 1.f, 1, 0);
    k_gemm<<<dim3(16, 4, 8), 256>>>(p_pA,  lat_out_w,  p_pLC,  Bn * Ln, Dn, Dn, 0, nullptr, 1.f, 8, S);
    k_gemm<<<dim3(16, 4, 8), 256>>>(p_pLC, lat_k_w,    p_pk2,  Bn * Ln, Dn, Dn, 0, nullptr, 1.f, 8, S);
    k_gemm<<<dim3(16, 4, 8), 256>>>(p_pLC, lat_v_w,    p_pB,   Bn * Ln, Dn, Dn, 0, nullptr, 1.f, 8, S);
    k_gemm<<<dim3(16, 4, 8), 256>>>(p_pB,  step_out_w, p_pC,   Bn * Ln, Dn, Dn, 0, nullptr, 1.f, 8, S);
    k_gemm<<<dim3(16, 4, 8), 256>>>(p_pC,  gate_w1 + (size_t)Dn * Dn, p_plvw, Bn * Ln, Dn, Dn, 0, nullptr, 1.f, 8, S);
    k_redN<<<S / 4 / 256, 256>>>((float4*)p_k2,  (const float4*)p_pk2,  S / 4, 8, S / 4);
    k_redN<<<S / 4 / 256, 256>>>((float4*)p_lvw, (const float4*)p_plvw, S / 4, 8, S / 4);

    // batch-independent path: step_base, then [P,D] GEMMs (split-K x4)
    k_stepbase<<<(pl * Dn + 255) / 256, 256>>>(qpos, ptbl, pl);
    int gy = (pl + 63) / 64;
    int n4p = pl * Dn / 4;
    k_gemm<<<dim3(16, gy, 4), 256>>>(p_sb, step_q_w, p_qb2p, pl, Dn, Dn, 0, nullptr, inv_sqrt_d, 1, 0);
    k_gemm<<<dim3(16, gy, 4), 256>>>(p_sb, gate_w1,  p_bhp,  pl, Dn, Dn, 0, nullptr, 1.f, 1, 0);
    k_redN<<<(n4p + 255) / 256, 256>>>((float4*)p_qb2, (const float4*)p_qb2p, n4p, 4, n4p);
    k_redN<<<(n4p + 255) / 256, 256>>>((float4*)p_bh,  (const float4*)p_bhp,  n4p, 4, n4p);

    // stage-2 attention weights
    k_s2<<<dim3((pl + 15) / 16, Bn), 256>>>(pl);

    // gate select + streaming expert combine
    const int smem_gs = (Ln * Dn + 16 * 1026 + Dn + 64 + 272 + 16) * 4;
    cudaFuncSetAttribute(k_gatesel, cudaFuncAttributeMaxDynamicSharedMemorySize, smem_gs);
    k_gatesel<<<dim3((pl + 7) / 8, Bn), 256, smem_gs>>>(gate_w2, gate_b2, gate_b1, pl);
    k_combine<<<pl, 256>>>(qexp, out, pl, Pfull);
}

// round 6
// speedup vs baseline: 1.7219x; 1.0460x over previous
#include <cuda_runtime.h>
#include <math.h>
#include <stdint.h>

#define Bn 32
#define Tn 2048
#define Dn 1024
#define En 16
#define Ln 8
#define Pmax 720
#define SUBSEG 32          // tokens per sub-segment (smem tile)
#define NSUB 4             // sub-segments per block
#define NPART 16           // stage-1 partial count = Tn/(SUBSEG*NSUB)

typedef unsigned long long ull;

__device__ __forceinline__ void fma2(ull& d, ull a, ull b) {
    asm("fma.rn.f32x2 %0, %1, %2, %0;" : "+l"(d) : "l"(a), "l"(b));
}
__device__ __forceinline__ float2 u2f(ull v) {
    float2 f; asm("mov.b64 {%0,%1}, %2;" : "=f"(f.x), "=f"(f.y) : "l"(v)); return f;
}
__device__ __forceinline__ float gelu_f(float x) {
    return 0.5f * x * (1.0f + erff(x * 0.70710678118654752440f));
}

// ---------------- scratch ----------------
__device__ float g_step_base[Pmax * Dn];
__device__ float g_t1p[8 * Ln * Dn];
__device__ float g_qeffp[8 * Ln * Dn];
__device__ float g_qeff[Ln * Dn];
__device__ float g_ssum[Bn * Ln * NPART];
__device__ float g_upart[(size_t)NPART * Bn * Ln * Dn];  // 16.8MB
__device__ float g_U[Bn * Ln * Dn];
__device__ float g_pA[8 * Bn * Ln * Dn];
__device__ float g_pLC[8 * Bn * Ln * Dn];
__device__ float g_pk2[8 * Bn * Ln * Dn];
__device__ float g_pB[8 * Bn * Ln * Dn];
__device__ float g_pC[8 * Bn * Ln * Dn];
__device__ float g_plvw[8 * Bn * Ln * Dn];
__device__ float g_k2[Bn * Ln * Dn];
__device__ float g_lvw[Bn * Ln * Dn];
__device__ float g_bcat[Dn * 2048];          // packed [step_q_w*scale | gate_w1a]
__device__ float g_pcat[2 * Pmax * 2048];    // split-K partials of [P,2048]
__device__ float g_qb2[Pmax * Dn];
__device__ float g_bh[Pmax * Dn];
__device__ float g_A2[Bn * Pmax * Ln];
__device__ float4 g_sel[Bn * Pmax];

// ---------------- step_base ----------------
__global__ void k_stepbase(const float* __restrict__ qpos,
                           const float* __restrict__ tbl, int pl) {
    int i = blockIdx.x * 256 + threadIdx.x;
    if (i < pl * Dn)
        g_step_base[i] = qpos[i] + tbl[(size_t)pl * Dn + (i & (Dn - 1))];
}

// ---------------- pack B for the fused P-GEMM ----------------
__global__ void k_pack(const float* __restrict__ sqw, const float* __restrict__ gw1,
                       float alpha) {
    int i = blockIdx.x * 256 + threadIdx.x;   // over 1024*2048/4 float4
    int row = i >> 9;        // 512 float4 per packed row
    int c4 = i & 511;
    float4 v;
    if (c4 < 256) {
        v = ((const float4*)sqw)[row * 256 + c4];
        v.x *= alpha; v.y *= alpha; v.z *= alpha; v.w *= alpha;
    } else {
        v = ((const float4*)gw1)[row * 256 + (c4 - 256)];
    }
    ((float4*)g_bcat)[i] = v;
}

// ---------------- split-K fp32x2 GEMM ----------------
#define GEMM_PREFETCH(k0)                                                        \
    {                                                                            \
        for (int r = 0; r < 4; r++) {                                            \
            int i = tid + 256 * r;                                               \
            int row = i >> 4, col = i & 15;                                      \
            int gm = m0 + row;                                                   \
            float v = 0.f;                                                       \
            if (gm < M) {                                                        \
                size_t off = (size_t)gm * K + (k0) + col;                        \
                v = A[off];                                                      \
                for (int s = 1; s < nsumA; s++) v += A[off + (size_t)s * strideA]; \
            }                                                                    \
            ra[r] = v;                                                           \
        }                                                                        \
        if (!transB) {                                                           \
            for (int r = 0; r < 4; r++) {                                        \
                int i = tid + 256 * r;                                           \
                rb[r] = B[(size_t)((k0) + (i >> 6)) * N + n0 + (i & 63)];        \
            }                                                                    \
        } else {                                                                 \
            for (int r = 0; r < 4; r++) {                                        \
                int i = tid + 256 * r;                                           \
                rb[r] = B[(size_t)(n0 + (i >> 4)) * K + (k0) + (i & 15)];        \
            }                                                                    \
        }                                                                        \
    }

#define GEMM_STORE(bf)                                                           \
    {                                                                            \
        for (int r = 0; r < 4; r++) {                                            \
            int i = tid + 256 * r;                                               \
            *(float2*)&As2[bf][i & 15][2 * (i >> 4)] = make_float2(ra[r], ra[r]); \
        }                                                                        \
        if (!transB) {                                                           \
            for (int r = 0; r < 4; r++) {                                        \
                int i = tid + 256 * r;                                           \
                Bs[bf][i >> 6][i & 63] = rb[r];                                  \
            }                                                                    \
        } else {                                                                 \
            for (int r = 0; r < 4; r++) {                                        \
                int i = tid + 256 * r;                                           \
                Bs[bf][i & 15][i >> 4] = rb[r];                                  \
            }                                                                    \
        }                                                                        \
    }

#define GEMM_COMPUTE(bf)                                                         \
    {                                                                            \
        _Pragma("unroll")                                                        \
        for (int kk = 0; kk < 16; kk++) {                                        \
            ulonglong2 a01 = *(const ulonglong2*)&As2[bf][kk][ty * 8];           \
            ulonglong2 a23 = *(const ulonglong2*)&As2[bf][kk][ty * 8 + 4];       \
            ulonglong2 bb  = *(const ulonglong2*)&Bs[bf][kk][tx * 4];            \
            fma2(acc[0][0], a01.x, bb.x); fma2(acc[0][1], a01.x, bb.y);          \
            fma2(acc[1][0], a01.y, bb.x); fma2(acc[1][1], a01.y, bb.y);          \
            fma2(acc[2][0], a23.x, bb.x); fma2(acc[2][1], a23.x, bb.y);          \
            fma2(acc[3][0], a23.y, bb.x); fma2(acc[3][1], a23.y, bb.y);          \
        }                                                                        \
    }

__global__ void k_gemm(const float* __restrict__ A, const float* __restrict__ B,
                       float* __restrict__ C, int M, int N, int K,
                       int transB, const float* __restrict__ bias, float alpha,
                       int nsumA, int strideA) {
    __shared__ float As2[2][16][136];
    __shared__ float Bs[2][16][68];
    int tid = threadIdx.x;
    int tx = tid & 15, ty = tid >> 4;
    int m0 = blockIdx.y * 64, n0 = blockIdx.x * 64;
    int kper = K / gridDim.z;
    int kbeg = blockIdx.z * kper;
    C += (size_t)blockIdx.z * M * N;
    int nk = kper / 16;

    ull acc[4][2];
#pragma unroll
    for (int i = 0; i < 4; i++) { acc[i][0] = 0ULL; acc[i][1] = 0ULL; }

    float ra[4], rb[4];
    int buf = 0;
    GEMM_PREFETCH(kbeg);
    GEMM_STORE(0);
    __syncthreads();
    for (int kt = 0; kt < nk; kt++) {
        if (kt + 1 < nk) GEMM_PREFETCH(kbeg + (kt + 1) * 16);
        GEMM_COMPUTE(buf);
        if (kt + 1 < nk) {
            GEMM_STORE(buf ^ 1);
            __syncthreads();
            buf ^= 1;
        }
    }
#pragma unroll
    for (int i = 0; i < 4; i++) {
        int m = m0 + ty * 4 + i;
        if (m >= M) continue;
        float2 p0 = u2f(acc[i][0]), p1 = u2f(acc[i][1]);
        float4 o;
        o.x = alpha * p0.x; o.y = alpha * p0.y;
        o.z = alpha * p1.x; o.w = alpha * p1.y;
        if (bias) {
            o.x += bias[n0 + tx * 4];     o.y += bias[n0 + tx * 4 + 1];
            o.z += bias[n0 + tx * 4 + 2]; o.w += bias[n0 + tx * 4 + 3];
        }
        *(float4*)&C[(size_t)m * N + n0 + tx * 4] = o;
    }
}

// ---------------- generic partial reduction ----------------
__global__ void k_redN(float4* __restrict__ dst, const float4* __restrict__ src,
                       int n4, int nparts, int stride4) {
    int i = blockIdx.x * 256 + threadIdx.x;
    if (i >= n4) return;
    float4 s = src[i];
    for (int p = 1; p < nparts; p++) {
        float4 t = src[i + (size_t)p * stride4];
        s.x += t.x; s.y += t.y; s.z += t.z; s.w += t.w;
    }
    dst[i] = s;
}

// ---------------- de-interleave + reduce the packed P-GEMM ----------------
__global__ void k_redsplit(int pl) {
    int i = blockIdx.x * 256 + threadIdx.x;   // over pl*Dn/4
    if (i >= pl * 256) return;                // Dn/4 = 256 float4 per row
    int p = i >> 8, d4 = i & 255;
    const float4* s = (const float4*)g_pcat;
    size_t base = (size_t)p * 512 + d4;       // packed row = 512 float4
    size_t part = (size_t)pl * 512;
    float4 a = s[base], b = s[base + part];
    float4 c = s[base + 256], d = s[base + 256 + part];
    float4 q, h;
    q.x = a.x + b.x; q.y = a.y + b.y; q.z = a.z + b.z; q.w = a.w + b.w;
    h.x = c.x + d.x; h.y = c.y + d.y; h.z = c.z + d.z; h.w = c.w + d.w;
    ((float4*)g_qb2)[i] = q;
    ((float4*)g_bh)[i] = h;
}

// ---------------- fused stage-1 (single DRAM pass, 512 threads) -------------------
// grid (NPART=16, Bn), 512 threads, ~164KB smem.
// 16 warps = 8 row-groups x 2 d-halves. Per sub-segment of 32 tokens:
//   phase A: warp (g,h) loads rows g*4..g*4+3, d-half h; stashes to smem;
//            computes half-dots for 8 l; halves combined via smem prt.
//   finalize: 256 threads do exp (shift-free softmax).
//   phase C: U[l][d] += p[l][t] * ck[t][d] from smem; thread owns 2 d.
__global__ void __launch_bounds__(512) k_fused1(const float* __restrict__ ctx) {
    extern __shared__ float smf[];
    float* qs  = smf;                    // 8*1024
    float* ck  = qs + Ln * Dn;           // 32*1024
    float* ps2 = ck + SUBSEG * Dn;       // 8*64 (dup pairs)
    float* prt = ps2 + Ln * 64;          // 32 tt * 16 (l*2+h)
    int tid = threadIdx.x;
    for (int i = tid; i < Ln * Dn / 4; i += 512)
        ((float4*)qs)[i] = ((const float4*)g_qeff)[i];
    int b = blockIdx.y;
    int w = tid >> 5, lane = tid & 31;
    int g = w >> 1, h = w & 1;

    ull uacc[Ln];
#pragma unroll
    for (int l = 0; l < Ln; l++) uacc[l] = 0ULL;
    float ssum = 0.f;  // warps 0-7: exp-sum for l = w

    for (int sub = 0; sub < NSUB; sub++) {
        int t0 = (blockIdx.x * NSUB + sub) * SUBSEG;
        const float* base = ctx + ((size_t)b * Tn + t0 + g * 4) * Dn + h * 512;
        __syncthreads();  // previous phase C done before overwriting ck/ps2/prt

        // phase A: 4 token rows x half-d per warp
        ull acc[4][Ln];
#pragma unroll
        for (int tt = 0; tt < 4; tt++)
#pragma unroll
            for (int l = 0; l < Ln; l++) acc[tt][l] = 0ULL;
#pragma unroll
        for (int i = 0; i < 4; i++) {
            int d = (lane + 32 * i) * 4;   // 0..508 within half
            ulonglong2 c0 = *(const ulonglong2*)(base + d);
            ulonglong2 c1 = *(const ulonglong2*)(base + Dn + d);
            ulonglong2 c2 = *(const ulonglong2*)(base + 2 * Dn + d);
            ulonglong2 c3 = *(const ulonglong2*)(base + 3 * Dn + d);
            int ckd = h * 512 + d;
            *(ulonglong2*)&ck[(g * 4 + 0) * Dn + ckd] = c0;
            *(ulonglong2*)&ck[(g * 4 + 1) * Dn + ckd] = c1;
            *(ulonglong2*)&ck[(g * 4 + 2) * Dn + ckd] = c2;
            *(ulonglong2*)&ck[(g * 4 + 3) * Dn + ckd] = c3;
#pragma unroll
            for (int l = 0; l < Ln; l++) {
                ulonglong2 q = *(const ulonglong2*)&qs[l * Dn + ckd];
                fma2(acc[0][l], c0.x, q.x); fma2(acc[0][l], c0.y, q.y);
                fma2(acc[1][l], c1.x, q.x); fma2(acc[1][l], c1.y, q.y);
                fma2(acc[2][l], c2.x, q.x); fma2(acc[2][l], c2.y, q.y);
                fma2(acc[3][l], c3.x, q.x); fma2(acc[3][l], c3.y, q.y);
            }
        }
#pragma unroll
        for (int tt = 0; tt < 4; tt++)
#pragma unroll
            for (int l = 0; l < Ln; l++) {
                float2 f = u2f(acc[tt][l]);
                float v = f.x + f.y;
                for (int off = 16; off; off >>= 1)
                    v += __shfl_xor_sync(0xffffffffu, v, off);
                if (lane == 0)
                    prt[(g * 4 + tt) * 16 + l * 2 + h] = v;
            }
        __syncthreads();

        // finalize: exp (shift-free softmax; scores tiny, clamp for safety)
        if (tid < 256) {
            int tt = tid >> 3, l = tid & 7;
            float v = prt[tt * 16 + l * 2] + prt[tt * 16 + l * 2 + 1];
            float e = expf(fminf(v, 60.0f));
            ps2[l * 64 + 2 * tt] = e;
            ps2[l * 64 + 2 * tt + 1] = e;
        }
        __syncthreads();

        // phase B: warps 0-7 accumulate exp-sum for l = w
        if (w < Ln) {
            float s = ps2[w * 64 + 2 * lane];
            for (int off = 16; off; off >>= 1)
                s += __shfl_xor_sync(0xffffffffu, s, off);
            ssum += s;
        }

        // phase C: U accumulation from smem; thread owns 2 d (f32x2)
        int d2 = tid * 2;
#pragma unroll 4
        for (int tt = 0; tt < SUBSEG; tt++) {
            ull c = *(const ull*)&ck[tt * Dn + d2];
#pragma unroll
            for (int l = 0; l < Ln; l++) {
                ull p = *(const ull*)&ps2[l * 64 + 2 * tt];
                fma2(uacc[l], p, c);
            }
        }
    }
#pragma unroll
    for (int l = 0; l < Ln; l++) {
        float2 f = u2f(uacc[l]);
        *(float2*)&g_upart[(((size_t)blockIdx.x * Bn + b) * Ln + l) * Dn + tid * 2] = f;
    }
    if (w < Ln && lane == 0)
        g_ssum[((size_t)b * Ln + w) * NPART + blockIdx.x] = ssum;
}

// ---------------- combine stage-1 partials: U = sum(upart)/sum(exp) --------------
__global__ void k_comb1() {
    __shared__ float inv[Ln];
    int b = blockIdx.y, dc = blockIdx.x;
    int tid = threadIdx.x;
    if (tid < Ln) {
        float s0 = 0.f, s1 = 0.f, s2 = 0.f, s3 = 0.f;
#pragma unroll
        for (int g = 0; g < NPART; g += 4) {
            s0 += g_ssum[((size_t)b * Ln + tid) * NPART + g];
            s1 += g_ssum[((size_t)b * Ln + tid) * NPART + g + 1];
            s2 += g_ssum[((size_t)b * Ln + tid) * NPART + g + 2];
            s3 += g_ssum[((size_t)b * Ln + tid) * NPART + g + 3];
        }
        inv[tid] = 1.0f / ((s0 + s1) + (s2 + s3));
    }
    __syncthreads();
    int dg = dc * 256 + tid;
#pragma unroll
    for (int l = 0; l < Ln; l++) {
        float a0 = 0.f, a1 = 0.f, a2 = 0.f, a3 = 0.f;
#pragma unroll
        for (int s = 0; s < NPART; s += 4) {
            a0 += g_upart[(((size_t)(s + 0) * Bn + b) * Ln + l) * Dn + dg];
            a1 += g_upart[(((size_t)(s + 1) * Bn + b) * Ln + l) * Dn + dg];
            a2 += g_upart[(((size_t)(s + 2) * Bn + b) * Ln + l) * Dn + dg];
            a3 += g_upart[(((size_t)(s + 3) * Bn + b) * Ln + l) * Dn + dg];
        }
        g_U[((size_t)b * Ln + l) * Dn + dg] = ((a0 + a1) + (a2 + a3)) * inv[l];
    }
}

// ---------------- stage-2 scores + softmax over L=8 ----------------
__global__ void k_s2(int pl) {
    __shared__ float ks[Ln][Dn];  // 32KB
    int tid = threadIdx.x, b = blockIdx.y;
    for (int i = tid; i < Ln * Dn / 4; i += 256)
        ((float4*)ks)[i] = ((const float4*)(g_k2 + (size_t)b * Ln * Dn))[i];
    __syncthreads();
    int w = tid >> 5, lane = tid & 31;
    int p0 = blockIdx.x * 16 + w * 2;
    if (p0 > pl - 2) p0 = pl - 2;
    ull acc[2][Ln];
#pragma unroll
    for (int pp = 0; pp < 2; pp++)
#pragma unroll
        for (int l = 0; l < Ln; l++) acc[pp][l] = 0ULL;
#pragma unroll
    for (int i = 0; i < 8; i++) {
        int d = (lane + 32 * i) * 4;
        ulonglong2 q0 = *(const ulonglong2*)(g_qb2 + (size_t)p0 * Dn + d);
        ulonglong2 q1 = *(const ulonglong2*)(g_qb2 + (size_t)(p0 + 1) * Dn + d);
#pragma unroll
        for (int l = 0; l < Ln; l++) {
            ulonglong2 k = *(const ulonglong2*)&ks[l][d];
            fma2(acc[0][l], q0.x, k.x); fma2(acc[0][l], q0.y, k.y);
            fma2(acc[1][l], q1.x, k.x); fma2(acc[1][l], q1.y, k.y);
        }
    }
#pragma unroll
    for (int pp = 0; pp < 2; pp++) {
        float v[Ln];
#pragma unroll
        for (int l = 0; l < Ln; l++) {
            float2 f = u2f(acc[pp][l]);
            float s = f.x + f.y;
            for (int off = 16; off; off >>= 1)
                s += __shfl_xor_sync(0xffffffffu, s, off);
            v[l] = s;
        }
        if (lane == 0) {
            int p = p0 + pp;
            if (p < pl) {
                float m = v[0];
#pragma unroll
                for (int l = 1; l < Ln; l++) m = fmaxf(m, v[l]);
                float e[Ln], s = 0.f;
#pragma unroll
                for (int l = 0; l < Ln; l++) { e[l] = expf(v[l] - m); s += e[l]; }
                float inv = 1.0f / s;
#pragma unroll
                for (int l = 0; l < Ln; l++)
                    g_A2[((size_t)b * pl + p) * Ln + l] = e[l] * inv;
            }
        }
    }
}

// ---------------- gate select: h = gelu(...), logits, top-2 -> g_sel -------------
__global__ void k_gatesel(const float* __restrict__ w2, const float* __restrict__ b2,
                          const float* __restrict__ b1, int pl) {
    extern __shared__ float sm[];
    float* lvws = sm;                    // 8192
    float* w2T  = lvws + Ln * Dn;        // 16*1026
    float* hs   = w2T + 16 * 1026;       // 1024
    float* a2s  = hs + Dn;               // 64
    float* part = a2s + 64;              // 272
    float* lg   = part + 272;            // 16
    int tid = threadIdx.x, b = blockIdx.y, p0 = blockIdx.x * 8;
    for (int i = tid; i < Ln * Dn / 4; i += 256)
        ((float4*)lvws)[i] = ((const float4*)(g_lvw + (size_t)b * Ln * Dn))[i];
    for (int i = tid; i < Dn * En; i += 256) {
        int d = i >> 4, e = i & 15;
        w2T[e * 1026 + d] = w2[i];
    }
    if (tid < 64) {
        int pi = tid >> 3, l = tid & 7;
        int p = p0 + pi;
        a2s[tid] = (p < pl) ? g_A2[((size_t)b * pl + p) * Ln + l] : 0.f;
    }
    float4 bh4[8];
#pragma unroll
    for (int pi = 0; pi < 8; pi++) {
        int p = p0 + pi;
        bh4[pi] = (p < pl) ? *(const float4*)(g_bh + (size_t)p * Dn + tid * 4)
                           : make_float4(0, 0, 0, 0);
    }
    float4 b1v = *(const float4*)(b1 + tid * 4);
    __syncthreads();
    int e_id = tid & 15, dseg = tid >> 4;
    for (int pi = 0; pi < 8; pi++) {
        int p = p0 + pi;
        if (p >= pl) break;  // block-uniform
        float4 s4 = bh4[pi];
        s4.x += b1v.x; s4.y += b1v.y; s4.z += b1v.z; s4.w += b1v.w;
#pragma unroll
        for (int l = 0; l < Ln; l++) {
            float a = a2s[pi * 8 + l];
            float4 v = ((const float4*)lvws)[l * (Dn / 4) + tid];
            s4.x += a * v.x; s4.y += a * v.y; s4.z += a * v.z; s4.w += a * v.w;
        }
        float4 h4;
        h4.x = gelu_f(s4.x); h4.y = gelu_f(s4.y);
        h4.z = gelu_f(s4.z); h4.w = gelu_f(s4.w);
        ((float4*)hs)[tid] = h4;
        __syncthreads();
        ull lacc = 0ULL;
        int dbase = dseg * 64;
#pragma unroll
        for (int j = 0; j < 32; j++) {
            ull h2 = *(const ull*)&hs[dbase + 2 * j];
            ull wv = *(const ull*)&w2T[e_id * 1026 + dbase + 2 * j];
            fma2(lacc, h2, wv);
        }
        float2 lf = u2f(lacc);
        part[dseg * 17 + e_id] = lf.x + lf.y;
        __syncthreads();
        if (tid < En) {
            float L = b2[tid];
#pragma unroll
            for (int g = 0; g < 16; g++) L += part[g * 17 + tid];
            lg[tid] = L;
        }
        __syncthreads();
        if (tid == 0) {
            float b1s = lg[0]; int e1 = 0;
#pragma unroll
            for (int e = 1; e < En; e++) if (lg[e] > b1s) { b1s = lg[e]; e1 = e; }
            float b2s = -3.4e38f; int e2 = 0;
#pragma unroll
            for (int e = 0; e < En; e++)
                if (e != e1 && lg[e] > b2s) { b2s = lg[e]; e2 = e; }
            float x2 = expf(b2s - b1s);
            float s = 1.f + x2;
            g_sel[(size_t)b * pl + p] = make_float4(
                1.f / s, x2 / s, __int_as_float(e1), __int_as_float(e2));
        }
        __syncthreads();
    }
}

// ---------------- combine experts ----------------
__global__ void k_combine(const float* __restrict__ qexp, float* __restrict__ out,
                          int pl, int Pfull) {
    __shared__ float4 sel[Bn];
    int p = blockIdx.x, tid = threadIdx.x;
    if (tid < Bn) sel[tid] = g_sel[(size_t)tid * pl + p];
    __syncthreads();
#pragma unroll 4
    for (int b = 0; b < Bn; b++) {
        float4 s = sel[b];
        int eA = __float_as_int(s.z), eB = __float_as_int(s.w);
        float4 va = *(const float4*)(qexp + ((size_t)eA * Pfull + p) * Dn + tid * 4);
        float4 vb = *(const float4*)(qexp + ((size_t)eB * Pfull + p) * Dn + tid * 4);
        float4 o;
        o.x = s.x * va.x + s.y * vb.x;
        o.y = s.x * va.y + s.y * vb.y;
        o.z = s.x * va.z + s.y * vb.z;
        o.w = s.x * va.w + s.y * vb.w;
        *(float4*)(out + ((size_t)b * pl + p) * Dn + tid * 4) = o;
    }
}

// ---------------- launch ----------------
extern "C" void kernel_launch(void* const* d_in, const int* in_sizes, int n_in,
                              void* d_out, int out_size) {
    const float* ctx        = (const float*)d_in[0];
    const float* qexp       = (const float*)d_in[1];
    const float* qpos       = (const float*)d_in[2];
    const float* ptbl       = (const float*)d_in[3];
    const float* lats       = (const float*)d_in[4];
    const float* lat_q_w    = (const float*)d_in[5];
    const float* ctx_k_w    = (const float*)d_in[6];
    const float* ctx_v_w    = (const float*)d_in[7];
    const float* lat_out_w  = (const float*)d_in[8];
    const float* step_q_w   = (const float*)d_in[9];
    const float* lat_k_w    = (const float*)d_in[10];
    const float* lat_v_w    = (const float*)d_in[11];
    const float* step_out_w = (const float*)d_in[12];
    const float* gate_w1    = (const float*)d_in[13];
    const float* gate_b1    = (const float*)d_in[14];
    const float* gate_w2    = (const float*)d_in[15];
    const float* gate_b2    = (const float*)d_in[16];
    float* out = (float*)d_out;

    int pl = out_size / (Bn * Dn);
    int Pfull = in_sizes[2] / Dn;

    float *p_t1p, *p_qeffp, *p_qeff, *p_U;
    float *p_pA, *p_pLC, *p_pk2, *p_pB, *p_pC, *p_plvw;
    float *p_k2, *p_lvw, *p_sb, *p_bcat, *p_pcat;
    cudaGetSymbolAddress((void**)&p_t1p, g_t1p);
    cudaGetSymbolAddress((void**)&p_qeffp, g_qeffp);
    cudaGetSymbolAddress((void**)&p_qeff, g_qeff);
    cudaGetSymbolAddress((void**)&p_U, g_U);
    cudaGetSymbolAddress((void**)&p_pA, g_pA);
    cudaGetSymbolAddress((void**)&p_pLC, g_pLC);
    cudaGetSymbolAddress((void**)&p_pk2, g_pk2);
    cudaGetSymbolAddress((void**)&p_pB, g_pB);
    cudaGetSymbolAddress((void**)&p_pC, g_pC);
    cudaGetSymbolAddress((void**)&p_plvw, g_plvw);
    cudaGetSymbolAddress((void**)&p_k2, g_k2);
    cudaGetSymbolAddress((void**)&p_lvw, g_lvw);
    cudaGetSymbolAddress((void**)&p_sb, g_step_base);
    cudaGetSymbolAddress((void**)&p_bcat, g_bcat);
    cudaGetSymbolAddress((void**)&p_pcat, g_pcat);

    const float inv_sqrt_d = 0.03125f;
    const int S = Bn * Ln * Dn;

    // launches 0-2: qeff = (latents @ lat_q_w) @ ctx_k_w^T / sqrt(D)
    k_gemm<<<dim3(16, 1, 8), 256>>>(lats, lat_q_w, p_t1p, Ln, Dn, Dn, 0, nullptr, 1.f, 1, 0);
    k_gemm<<<dim3(16, 1, 8), 256>>>(p_t1p, ctx_k_w, p_qeffp, Ln, Dn, Dn, 1, nullptr, inv_sqrt_d, 8, Ln * Dn);
    k_redN<<<8, 256>>>((float4*)p_qeff, (const float4*)p_qeffp, Ln * Dn / 4, 8, Ln * Dn / 4);

    // launch 3 (ncu-sampled): fused stage-1, single DRAM pass, 512 threads
    const int smem_f1 = (Ln * Dn + SUBSEG * Dn + Ln * 64 + SUBSEG * 16) * 4;
    cudaFuncSetAttribute(k_fused1, cudaFuncAttributeMaxDynamicSharedMemorySize, smem_f1);
    k_fused1<<<dim3(NPART, Bn), 512, smem_f1>>>(ctx);
    k_comb1<<<dim3(4, Bn), 256>>>();

    // chain of [256,1024]x[1024,1024] GEMMs (split-K x8)
    k_gemm<<<dim3(16, 4, 8), 256>>>(p_U,   ctx_v_w,    p_pA,   Bn * Ln, Dn, Dn, 0, nullptr, 1.f, 1, 0);
    k_gemm<<<dim3(16, 4, 8), 256>>>(p_pA,  lat_out_w,  p_pLC,  Bn * Ln, Dn, Dn, 0, nullptr, 1.f, 8, S);
    k_gemm<<<dim3(16, 4, 8), 256>>>(p_pLC, lat_k_w,    p_pk2,  Bn * Ln, Dn, Dn, 0, nullptr, 1.f, 8, S);
    k_gemm<<<dim3(16, 4, 8), 256>>>(p_pLC, lat_v_w,    p_pB,   Bn * Ln, Dn, Dn, 0, nullptr, 1.f, 8, S);
    k_gemm<<<dim3(16, 4, 8), 256>>>(p_pB,  step_out_w, p_pC,   Bn * Ln, Dn, Dn, 0, nullptr, 1.f, 8, S);
    k_gemm<<<dim3(16, 4, 8), 256>>>(p_pC,  gate_w1 + (size_t)Dn * Dn, p_plvw, Bn * Ln, Dn, Dn, 0, nullptr, 1.f, 8, S);
    k_redN<<<S / 4 / 256, 256>>>((float4*)p_k2,  (const float4*)p_pk2,  S / 4, 8, S / 4);
    k_redN<<<S / 4 / 256, 256>>>((float4*)p_lvw, (const float4*)p_plvw, S / 4, 8, S / 4);

    // batch-independent path: step_base, packed [P,2048] GEMM (split-K x2)
    k_stepbase<<<(pl * Dn + 255) / 256, 256>>>(qpos, ptbl, pl);
    k_pack<<<Dn * 2048 / 4 / 256, 256>>>(step_q_w, gate_w1, inv_sqrt_d);
    int gy = (pl + 63) / 64;
    k_gemm<<<dim3(32, gy, 2), 256>>>(p_sb, p_bcat, p_pcat, pl, 2048, Dn, 0, nullptr, 1.f, 1, 0);
    k_redsplit<<<(pl * 256 + 255) / 256, 256>>>(pl);

    // stage-2 attention weights
    k_s2<<<dim3((pl + 15) / 16, Bn), 256>>>(pl);

    // gate select + streaming expert combine
    const int smem_gs = (Ln * Dn + 16 * 1026 + Dn + 64 + 272 + 16) * 4;
    cudaFuncSetAttribute(k_gatesel, cudaFuncAttributeMaxDynamicSharedMemorySize, smem_gs);
    k_gatesel<<<dim3((pl + 7) / 8, Bn), 256, smem_gs>>>(gate_w2, gate_b2, gate_b1, pl);
    k_combine<<<pl, 256>>>(qexp, out, pl, Pfull);
}